// round 1
// baseline (speedup 1.0000x reference)
#include <cuda_runtime.h>
#include <math.h>

// ---------------- problem constants ----------------
#define T_TOK 2048          // B*S
#define S_LEN 1024
#define H_DIM 1024
#define NHEAD 16
#define HD    64
#define NEXP  8
#define INTER 2816

// ---------------- device scratch (no allocs allowed) ----------------
__device__ float g_qkv [(size_t)T_TOK * 3 * H_DIM];      // 25 MB
__device__ float g_ctx [(size_t)T_TOK * H_DIM];
__device__ float g_tmp [(size_t)T_TOK * H_DIM];
__device__ float g_hs  [(size_t)T_TOK * H_DIM];
__device__ float g_act [(size_t)T_TOK * 2 * INTER];      // 46 MB
__device__ float g_ypair[(size_t)T_TOK * 2 * H_DIM];     // 17 MB
__device__ float g_pairw[T_TOK * 2];
__device__ int   g_cnt [NEXP];
__device__ int   g_rows[NEXP * T_TOK];

// ---------------- generic fp32 SGEMM: C[M,N] = A[M,K] @ B[K,N] ----------------
// BM=128, BN=64, BK=16, 256 threads, 8x4 micro-tile. Dims must be multiples.
__global__ __launch_bounds__(256) void sgemm_kernel(
    const float* __restrict__ A, const float* __restrict__ B,
    float* __restrict__ C, int M, int N, int K)
{
    __shared__ float As[16][128];
    __shared__ float Bs[16][64];
    int tx = threadIdx.x;
    int rowBase = blockIdx.y * 128;
    int colBase = blockIdx.x * 64;
    int ar = tx >> 1, ak = (tx & 1) * 8;
    int br = tx >> 4, bc = (tx & 15) * 4;
    int tr = tx >> 4, tc = tx & 15;

    float acc[8][4];
#pragma unroll
    for (int i = 0; i < 8; i++)
#pragma unroll
        for (int j = 0; j < 4; j++) acc[i][j] = 0.f;

    for (int kk = 0; kk < K; kk += 16) {
        const float* ap = A + (size_t)(rowBase + ar) * K + kk + ak;
        float4 a0 = *(const float4*)ap;
        float4 a1 = *(const float4*)(ap + 4);
        As[ak + 0][ar] = a0.x; As[ak + 1][ar] = a0.y;
        As[ak + 2][ar] = a0.z; As[ak + 3][ar] = a0.w;
        As[ak + 4][ar] = a1.x; As[ak + 5][ar] = a1.y;
        As[ak + 6][ar] = a1.z; As[ak + 7][ar] = a1.w;
        *(float4*)&Bs[br][bc] = *(const float4*)(B + (size_t)(kk + br) * N + colBase + bc);
        __syncthreads();
#pragma unroll
        for (int k = 0; k < 16; k++) {
            float a[8], b[4];
#pragma unroll
            for (int i = 0; i < 8; i++) a[i] = As[k][tr * 8 + i];
#pragma unroll
            for (int j = 0; j < 4; j++) b[j] = Bs[k][tc * 4 + j];
#pragma unroll
            for (int i = 0; i < 8; i++)
#pragma unroll
                for (int j = 0; j < 4; j++) acc[i][j] += a[i] * b[j];
        }
        __syncthreads();
    }
#pragma unroll
    for (int i = 0; i < 8; i++) {
        size_t row = (size_t)(rowBase + tr * 8 + i);
#pragma unroll
        for (int j = 0; j < 4; j++)
            C[row * N + colBase + tc * 4 + j] = acc[i][j];
    }
}

// ---------------- RoPE (in-place on q,k inside g_qkv) ----------------
__global__ void rope_kernel(const float* __restrict__ cosp, const float* __restrict__ sinp)
{
    int idx = blockIdx.x * blockDim.x + threadIdx.x;   // T*NH*32
    if (idx >= T_TOK * NHEAD * 32) return;
    int d = idx & 31;
    int n = (idx >> 5) & 15;
    int t = idx >> 9;
    int s = t & (S_LEN - 1);
    float c1 = cosp[s * 64 + d],      s1 = sinp[s * 64 + d];
    float c2 = cosp[s * 64 + d + 32], s2 = sinp[s * 64 + d + 32];
    size_t base = (size_t)t * 3072 + n * 64 + d;
    // q
    float x1 = g_qkv[base], x2 = g_qkv[base + 32];
    g_qkv[base]      = x1 * c1 - x2 * s1;
    g_qkv[base + 32] = x2 * c2 + x1 * s2;
    // k
    base += 1024;
    x1 = g_qkv[base]; x2 = g_qkv[base + 32];
    g_qkv[base]      = x1 * c1 - x2 * s1;
    g_qkv[base + 32] = x2 * c2 + x1 * s2;
}

// ---------------- attention: flash-style, one block per (b,h,qtile64) ----------------
__global__ __launch_bounds__(256) void attn_kernel()
{
    extern __shared__ float sm[];
    float* Qs = sm;                 // 64 x 65
    float* Ks = sm + 64 * 65;
    float* Vs = sm + 2 * 64 * 65;

    int qt = blockIdx.x, h = blockIdx.y, b = blockIdx.z;
    int tx = threadIdx.x;
    int row = tx >> 2, sub = tx & 3;
    int tbase = b * S_LEN;

    // load Q tile
    {
        int lr = tx >> 2, lc = (tx & 3) * 16;
        const float* qp = g_qkv + (size_t)(tbase + qt * 64 + lr) * 3072 + h * 64;
#pragma unroll
        for (int i = 0; i < 4; i++) {
            int c = lc + i * 4;
            float4 v = *(const float4*)(qp + c);
            Qs[lr * 65 + c]     = v.x; Qs[lr * 65 + c + 1] = v.y;
            Qs[lr * 65 + c + 2] = v.z; Qs[lr * 65 + c + 3] = v.w;
        }
    }

    float acc[64];
#pragma unroll
    for (int i = 0; i < 64; i++) acc[i] = 0.f;
    float m = -1e30f, l = 0.f;

    for (int kt = 0; kt < 16; kt++) {
        __syncthreads();
        {
            int lr = tx >> 2, lc = (tx & 3) * 16;
            const float* kp = g_qkv + (size_t)(tbase + kt * 64 + lr) * 3072 + 1024 + h * 64;
            const float* vp = kp + 1024;
#pragma unroll
            for (int i = 0; i < 4; i++) {
                int c = lc + i * 4;
                float4 kv = *(const float4*)(kp + c);
                Ks[lr * 65 + c]     = kv.x; Ks[lr * 65 + c + 1] = kv.y;
                Ks[lr * 65 + c + 2] = kv.z; Ks[lr * 65 + c + 3] = kv.w;
                float4 vv = *(const float4*)(vp + c);
                Vs[lr * 65 + c]     = vv.x; Vs[lr * 65 + c + 1] = vv.y;
                Vs[lr * 65 + c + 2] = vv.z; Vs[lr * 65 + c + 3] = vv.w;
            }
        }
        __syncthreads();

        float sc[16];
#pragma unroll
        for (int jt = 0; jt < 16; jt++) sc[jt] = 0.f;
#pragma unroll
        for (int d = 0; d < 64; d++) {
            float qd = Qs[row * 65 + d];
#pragma unroll
            for (int jt = 0; jt < 16; jt++)
                sc[jt] += qd * Ks[(sub * 16 + jt) * 65 + d];
        }
        float lm = -1e30f;
#pragma unroll
        for (int jt = 0; jt < 16; jt++) { sc[jt] *= 0.125f; lm = fmaxf(lm, sc[jt]); }
        lm = fmaxf(lm, __shfl_xor_sync(0xffffffffu, lm, 1));
        lm = fmaxf(lm, __shfl_xor_sync(0xffffffffu, lm, 2));
        float mn = fmaxf(m, lm);
        float alpha = __expf(m - mn);
        l *= alpha;
#pragma unroll
        for (int d = 0; d < 64; d++) acc[d] *= alpha;
#pragma unroll
        for (int jt = 0; jt < 16; jt++) {
            int j = sub * 16 + jt;
            float p = __expf(sc[jt] - mn);
            l += p;
#pragma unroll
            for (int d = 0; d < 64; d++) acc[d] += p * Vs[j * 65 + d];
        }
        m = mn;
    }

    // reduce 4 sub-threads per row
    l += __shfl_xor_sync(0xffffffffu, l, 1);
    l += __shfl_xor_sync(0xffffffffu, l, 2);
#pragma unroll
    for (int d = 0; d < 64; d++) {
        acc[d] += __shfl_xor_sync(0xffffffffu, acc[d], 1);
        acc[d] += __shfl_xor_sync(0xffffffffu, acc[d], 2);
    }
    float inv = 1.f / l;
    int t = tbase + qt * 64 + row;
#pragma unroll
    for (int i = 0; i < 16; i++) {
        int d = sub * 16 + i;
        g_ctx[(size_t)t * H_DIM + h * 64 + d] = acc[d] * inv;
    }
}

// ---------------- block reduce helper ----------------
__device__ __forceinline__ float blockReduceSum(float v)
{
    __shared__ float red[8];
    int lane = threadIdx.x & 31, warp = threadIdx.x >> 5;
#pragma unroll
    for (int o = 16; o; o >>= 1) v += __shfl_xor_sync(0xffffffffu, v, o);
    if (lane == 0) red[warp] = v;
    __syncthreads();
    if (warp == 0) {
        float t = (lane < 8) ? red[lane] : 0.f;
#pragma unroll
        for (int o = 4; o; o >>= 1) t += __shfl_xor_sync(0xffffffffu, t, o);
        if (lane == 0) red[0] = t;
    }
    __syncthreads();
    return red[0];
}

// ---------------- residual add + rmsnorm: hs = rmsnorm(a+b) ----------------
__global__ __launch_bounds__(256) void addnorm_kernel(
    const float* __restrict__ a, const float* __restrict__ b, float* __restrict__ out)
{
    int t = blockIdx.x, tx = threadIdx.x;
    const float* ap = a + (size_t)t * H_DIM;
    const float* bp = b + (size_t)t * H_DIM;
    float v[4]; float ss = 0.f;
#pragma unroll
    for (int j = 0; j < 4; j++) {
        int i = tx + j * 256;
        float x = ap[i] + bp[i];
        v[j] = x; ss += x * x;
    }
    float tot = blockReduceSum(ss);
    float scale = rsqrtf(tot * (1.f / H_DIM) + 1e-5f);
    float* op = out + (size_t)t * H_DIM;
#pragma unroll
    for (int j = 0; j < 4; j++) op[tx + j * 256] = v[j] * scale;
}

// ---------------- routing ----------------
__global__ void zerocnt_kernel() { if (threadIdx.x < NEXP) g_cnt[threadIdx.x] = 0; }

__global__ void route_kernel(const float* __restrict__ wg)
{
    int t = blockIdx.x, lane = threadIdx.x;     // 32 threads
    float p[8];
#pragma unroll
    for (int e = 0; e < 8; e++) p[e] = 0.f;
    const float* x = g_hs + (size_t)t * H_DIM;
    for (int h = lane; h < H_DIM; h += 32) {
        float xv = x[h];
#pragma unroll
        for (int e = 0; e < 8; e++) p[e] += xv * wg[h * 8 + e];
    }
#pragma unroll
    for (int e = 0; e < 8; e++)
#pragma unroll
        for (int o = 16; o; o >>= 1) p[e] += __shfl_xor_sync(0xffffffffu, p[e], o);

    if (lane == 0) {
        int e0 = 0; float l0 = p[0];
        for (int e = 1; e < 8; e++) if (p[e] > l0) { l0 = p[e]; e0 = e; }
        int e1 = -1; float l1 = -1e30f;
        for (int e = 0; e < 8; e++) if (e != e0 && p[e] > l1) { l1 = p[e]; e1 = e; }
        float w0 = 1.f / (1.f + expf(l1 - l0));   // = softmax-topk renormalized
        float w1 = 1.f - w0;
        int pos0 = atomicAdd(&g_cnt[e0], 1);
        g_rows[e0 * T_TOK + pos0] = t * 2;
        g_pairw[t * 2] = w0;
        int pos1 = atomicAdd(&g_cnt[e1], 1);
        g_rows[e1 * T_TOK + pos1] = t * 2 + 1;
        g_pairw[t * 2 + 1] = w1;
    }
}

// ---------------- MoE gate_up: act[pid, j] = silu(x@Wg) * (x@Wu) ----------------
__global__ __launch_bounds__(256) void moe_gateup_kernel(const float* __restrict__ w)
{
    int e = blockIdx.z;
    int count = g_cnt[e];
    int mBase = blockIdx.y * 128;
    if (mBase >= count) return;
    int nBase = blockIdx.x * 64;

    __shared__ float As[16][128];
    __shared__ float Bg[16][64];
    __shared__ float Bu[16][64];
    __shared__ int   sPid[128];

    int tx = threadIdx.x;
    if (tx < 128) {
        int r = mBase + tx;
        sPid[tx] = (r < count) ? g_rows[e * T_TOK + r] : -1;
    }
    __syncthreads();

    const float* We = w + (size_t)e * H_DIM * (2 * INTER);
    int ar = tx >> 1, ak = (tx & 1) * 8;
    int br = tx >> 4, bc = (tx & 15) * 4;
    int tr = tx >> 4, tc = tx & 15;
    int pidA = sPid[ar];
    const float* Arow = (pidA >= 0) ? (g_hs + (size_t)(pidA >> 1) * H_DIM) : g_hs;
    bool valid = pidA >= 0;

    float accG[8][4], accU[8][4];
#pragma unroll
    for (int i = 0; i < 8; i++)
#pragma unroll
        for (int j = 0; j < 4; j++) { accG[i][j] = 0.f; accU[i][j] = 0.f; }

    for (int kk = 0; kk < H_DIM; kk += 16) {
        float4 a0, a1;
        if (valid) { a0 = *(const float4*)(Arow + kk + ak); a1 = *(const float4*)(Arow + kk + ak + 4); }
        else       { a0 = make_float4(0,0,0,0); a1 = a0; }
        As[ak + 0][ar] = a0.x; As[ak + 1][ar] = a0.y; As[ak + 2][ar] = a0.z; As[ak + 3][ar] = a0.w;
        As[ak + 4][ar] = a1.x; As[ak + 5][ar] = a1.y; As[ak + 6][ar] = a1.z; As[ak + 7][ar] = a1.w;
        const float* bp = We + (size_t)(kk + br) * (2 * INTER) + nBase + bc;
        *(float4*)&Bg[br][bc] = *(const float4*)bp;
        *(float4*)&Bu[br][bc] = *(const float4*)(bp + INTER);
        __syncthreads();
#pragma unroll
        for (int k = 0; k < 16; k++) {
            float a[8], gb[4], ub[4];
#pragma unroll
            for (int i = 0; i < 8; i++) a[i] = As[k][tr * 8 + i];
#pragma unroll
            for (int j = 0; j < 4; j++) { gb[j] = Bg[k][tc * 4 + j]; ub[j] = Bu[k][tc * 4 + j]; }
#pragma unroll
            for (int i = 0; i < 8; i++)
#pragma unroll
                for (int j = 0; j < 4; j++) { accG[i][j] += a[i] * gb[j]; accU[i][j] += a[i] * ub[j]; }
        }
        __syncthreads();
    }
#pragma unroll
    for (int i = 0; i < 8; i++) {
        int pid = sPid[tr * 8 + i];
        if (pid >= 0) {
            float* dst = g_act + (size_t)pid * INTER + nBase + tc * 4;
#pragma unroll
            for (int j = 0; j < 4; j++) {
                float gv = accG[i][j];
                float sg = gv / (1.f + __expf(-gv));
                dst[j] = sg * accU[i][j];
            }
        }
    }
}

// ---------------- MoE down: ypair[pid,:] = w_pid * (act[pid] @ Wd[e]) ----------------
__global__ __launch_bounds__(256) void moe_down_kernel(const float* __restrict__ wd)
{
    int e = blockIdx.z;
    int count = g_cnt[e];
    int mBase = blockIdx.y * 128;
    if (mBase >= count) return;
    int nBase = blockIdx.x * 64;

    __shared__ float As[16][128];
    __shared__ float Bs[16][64];
    __shared__ int   sPid[128];

    int tx = threadIdx.x;
    if (tx < 128) {
        int r = mBase + tx;
        sPid[tx] = (r < count) ? g_rows[e * T_TOK + r] : -1;
    }
    __syncthreads();

    const float* We = wd + (size_t)e * INTER * H_DIM;
    int ar = tx >> 1, ak = (tx & 1) * 8;
    int br = tx >> 4, bc = (tx & 15) * 4;
    int tr = tx >> 4, tc = tx & 15;
    int pidA = sPid[ar];
    const float* Arow = (pidA >= 0) ? (g_act + (size_t)pidA * INTER) : g_act;
    bool valid = pidA >= 0;

    float acc[8][4];
#pragma unroll
    for (int i = 0; i < 8; i++)
#pragma unroll
        for (int j = 0; j < 4; j++) acc[i][j] = 0.f;

    for (int kk = 0; kk < INTER; kk += 16) {
        float4 a0, a1;
        if (valid) { a0 = *(const float4*)(Arow + kk + ak); a1 = *(const float4*)(Arow + kk + ak + 4); }
        else       { a0 = make_float4(0,0,0,0); a1 = a0; }
        As[ak + 0][ar] = a0.x; As[ak + 1][ar] = a0.y; As[ak + 2][ar] = a0.z; As[ak + 3][ar] = a0.w;
        As[ak + 4][ar] = a1.x; As[ak + 5][ar] = a1.y; As[ak + 6][ar] = a1.z; As[ak + 7][ar] = a1.w;
        *(float4*)&Bs[br][bc] = *(const float4*)(We + (size_t)(kk + br) * H_DIM + nBase + bc);
        __syncthreads();
#pragma unroll
        for (int k = 0; k < 16; k++) {
            float a[8], b[4];
#pragma unroll
            for (int i = 0; i < 8; i++) a[i] = As[k][tr * 8 + i];
#pragma unroll
            for (int j = 0; j < 4; j++) b[j] = Bs[k][tc * 4 + j];
#pragma unroll
            for (int i = 0; i < 8; i++)
#pragma unroll
                for (int j = 0; j < 4; j++) acc[i][j] += a[i] * b[j];
        }
        __syncthreads();
    }
#pragma unroll
    for (int i = 0; i < 8; i++) {
        int pid = sPid[tr * 8 + i];
        if (pid >= 0) {
            float wgt = g_pairw[pid];
            float* dst = g_ypair + (size_t)pid * H_DIM + nBase + tc * 4;
#pragma unroll
            for (int j = 0; j < 4; j++) dst[j] = wgt * acc[i][j];
        }
    }
}

// ---------------- final: out = rmsnorm(hs + y0 + y1) ----------------
__global__ __launch_bounds__(256) void final_kernel(float* __restrict__ out)
{
    int t = blockIdx.x, tx = threadIdx.x;
    const float* hs = g_hs + (size_t)t * H_DIM;
    const float* y0 = g_ypair + (size_t)(t * 2) * H_DIM;
    const float* y1 = y0 + H_DIM;
    float v[4]; float ss = 0.f;
#pragma unroll
    for (int j = 0; j < 4; j++) {
        int i = tx + j * 256;
        float x = hs[i] + y0[i] + y1[i];
        v[j] = x; ss += x * x;
    }
    float tot = blockReduceSum(ss);
    float scale = rsqrtf(tot * (1.f / H_DIM) + 1e-5f);
    float* op = out + (size_t)t * H_DIM;
#pragma unroll
    for (int j = 0; j < 4; j++) op[tx + j * 256] = v[j] * scale;
}

// ---------------- launch ----------------
extern "C" void kernel_launch(void* const* d_in, const int* in_sizes, int n_in,
                              void* d_out, int out_size)
{
    const float* hidden = (const float*)d_in[0];
    const float* cosp   = (const float*)d_in[1];
    const float* sinp   = (const float*)d_in[2];
    const float* w_qkv  = (const float*)d_in[3];
    const float* w_o    = (const float*)d_in[4];
    const float* w_gate = (const float*)d_in[5];
    const float* w_gu   = (const float*)d_in[6];
    const float* w_down = (const float*)d_in[7];
    float* out = (float*)d_out;

    float* qkv_ptr; cudaGetSymbolAddress((void**)&qkv_ptr, g_qkv);
    float* ctx_ptr; cudaGetSymbolAddress((void**)&ctx_ptr, g_ctx);
    float* tmp_ptr; cudaGetSymbolAddress((void**)&tmp_ptr, g_tmp);
    float* hs_ptr;  cudaGetSymbolAddress((void**)&hs_ptr,  g_hs);

    // 1. QKV projection: [2048,1024] x [1024,3072]
    sgemm_kernel<<<dim3(3072 / 64, 2048 / 128), 256>>>(hidden, w_qkv, qkv_ptr, 2048, 3072, 1024);

    // 2. RoPE in-place on q,k
    rope_kernel<<<(T_TOK * NHEAD * 32) / 256, 256>>>(cosp, sinp);

    // 3. attention
    cudaFuncSetAttribute(attn_kernel, cudaFuncAttributeMaxDynamicSharedMemorySize, 3 * 64 * 65 * 4);
    attn_kernel<<<dim3(16, 16, 2), 256, 3 * 64 * 65 * 4>>>();

    // 4. O projection
    sgemm_kernel<<<dim3(1024 / 64, 2048 / 128), 256>>>(ctx_ptr, w_o, tmp_ptr, 2048, 1024, 1024);

    // 5. hs = rmsnorm(x + attn_out)
    addnorm_kernel<<<T_TOK, 256>>>(hidden, tmp_ptr, hs_ptr);

    // 6. routing
    zerocnt_kernel<<<1, 32>>>();
    route_kernel<<<T_TOK, 32>>>(w_gate);

    // 7. expert gate_up + silu  (grid worst-case, early exit by count)
    moe_gateup_kernel<<<dim3(INTER / 64, 2048 / 128, NEXP), 256>>>(w_gu);

    // 8. expert down proj (weighted)
    moe_down_kernel<<<dim3(1024 / 64, 2048 / 128, NEXP), 256>>>(w_down);

    // 9. out = rmsnorm(hs + mixed)
    final_kernel<<<T_TOK, 256>>>(out);
}

// round 2
// speedup vs baseline: 1.0004x; 1.0004x over previous
#include <cuda_runtime.h>
#include <math.h>

// ---------------- problem constants ----------------
#define T_TOK 2048          // B*S
#define S_LEN 1024
#define H_DIM 1024
#define NHEAD 16
#define HD    64
#define NEXP  8
#define INTER 2816

// ---------------- device scratch (no allocs allowed) ----------------
__device__ float g_qkv [(size_t)T_TOK * 3 * H_DIM];      // 25 MB
__device__ float g_ctx [(size_t)T_TOK * H_DIM];
__device__ float g_tmp [(size_t)T_TOK * H_DIM];
__device__ float g_hs  [(size_t)T_TOK * H_DIM];
__device__ float g_act [(size_t)T_TOK * 2 * INTER];      // 46 MB
__device__ float g_ypair[(size_t)T_TOK * 2 * H_DIM];     // 17 MB
__device__ float g_pairw[T_TOK * 2];
__device__ int   g_cnt [NEXP];
__device__ int   g_rows[NEXP * T_TOK];

// ---------------- generic fp32 SGEMM: C[M,N] = A[M,K] @ B[K,N] ----------------
// BM=128, BN=64, BK=16, 256 threads, 8x4 micro-tile. Dims must be multiples.
__global__ __launch_bounds__(256) void sgemm_kernel(
    const float* __restrict__ A, const float* __restrict__ B,
    float* __restrict__ C, int M, int N, int K)
{
    __shared__ float As[16][128];
    __shared__ float Bs[16][64];
    int tx = threadIdx.x;
    int rowBase = blockIdx.y * 128;
    int colBase = blockIdx.x * 64;
    int ar = tx >> 1, ak = (tx & 1) * 8;
    int br = tx >> 4, bc = (tx & 15) * 4;
    int tr = tx >> 4, tc = tx & 15;

    float acc[8][4];
#pragma unroll
    for (int i = 0; i < 8; i++)
#pragma unroll
        for (int j = 0; j < 4; j++) acc[i][j] = 0.f;

    for (int kk = 0; kk < K; kk += 16) {
        const float* ap = A + (size_t)(rowBase + ar) * K + kk + ak;
        float4 a0 = *(const float4*)ap;
        float4 a1 = *(const float4*)(ap + 4);
        As[ak + 0][ar] = a0.x; As[ak + 1][ar] = a0.y;
        As[ak + 2][ar] = a0.z; As[ak + 3][ar] = a0.w;
        As[ak + 4][ar] = a1.x; As[ak + 5][ar] = a1.y;
        As[ak + 6][ar] = a1.z; As[ak + 7][ar] = a1.w;
        *(float4*)&Bs[br][bc] = *(const float4*)(B + (size_t)(kk + br) * N + colBase + bc);
        __syncthreads();
#pragma unroll
        for (int k = 0; k < 16; k++) {
            float a[8], b[4];
#pragma unroll
            for (int i = 0; i < 8; i++) a[i] = As[k][tr * 8 + i];
#pragma unroll
            for (int j = 0; j < 4; j++) b[j] = Bs[k][tc * 4 + j];
#pragma unroll
            for (int i = 0; i < 8; i++)
#pragma unroll
                for (int j = 0; j < 4; j++) acc[i][j] += a[i] * b[j];
        }
        __syncthreads();
    }
#pragma unroll
    for (int i = 0; i < 8; i++) {
        size_t row = (size_t)(rowBase + tr * 8 + i);
#pragma unroll
        for (int j = 0; j < 4; j++)
            C[row * N + colBase + tc * 4 + j] = acc[i][j];
    }
}

// ---------------- RoPE (in-place on q,k inside g_qkv) ----------------
__global__ void rope_kernel(const float* __restrict__ cosp, const float* __restrict__ sinp)
{
    int idx = blockIdx.x * blockDim.x + threadIdx.x;   // T*NH*32
    if (idx >= T_TOK * NHEAD * 32) return;
    int d = idx & 31;
    int n = (idx >> 5) & 15;
    int t = idx >> 9;
    int s = t & (S_LEN - 1);
    float c1 = cosp[s * 64 + d],      s1 = sinp[s * 64 + d];
    float c2 = cosp[s * 64 + d + 32], s2 = sinp[s * 64 + d + 32];
    size_t base = (size_t)t * 3072 + n * 64 + d;
    // q
    float x1 = g_qkv[base], x2 = g_qkv[base + 32];
    g_qkv[base]      = x1 * c1 - x2 * s1;
    g_qkv[base + 32] = x2 * c2 + x1 * s2;
    // k
    base += 1024;
    x1 = g_qkv[base]; x2 = g_qkv[base + 32];
    g_qkv[base]      = x1 * c1 - x2 * s1;
    g_qkv[base + 32] = x2 * c2 + x1 * s2;
}

// ---------------- attention: flash-style, one block per (b,h,qtile64) ----------------
__global__ __launch_bounds__(256) void attn_kernel()
{
    extern __shared__ float sm[];
    float* Qs = sm;                 // 64 x 65
    float* Ks = sm + 64 * 65;
    float* Vs = sm + 2 * 64 * 65;

    int qt = blockIdx.x, h = blockIdx.y, b = blockIdx.z;
    int tx = threadIdx.x;
    int row = tx >> 2, sub = tx & 3;
    int tbase = b * S_LEN;

    // load Q tile
    {
        int lr = tx >> 2, lc = (tx & 3) * 16;
        const float* qp = g_qkv + (size_t)(tbase + qt * 64 + lr) * 3072 + h * 64;
#pragma unroll
        for (int i = 0; i < 4; i++) {
            int c = lc + i * 4;
            float4 v = *(const float4*)(qp + c);
            Qs[lr * 65 + c]     = v.x; Qs[lr * 65 + c + 1] = v.y;
            Qs[lr * 65 + c + 2] = v.z; Qs[lr * 65 + c + 3] = v.w;
        }
    }

    float acc[64];
#pragma unroll
    for (int i = 0; i < 64; i++) acc[i] = 0.f;
    float m = -1e30f, l = 0.f;

    for (int kt = 0; kt < 16; kt++) {
        __syncthreads();
        {
            int lr = tx >> 2, lc = (tx & 3) * 16;
            const float* kp = g_qkv + (size_t)(tbase + kt * 64 + lr) * 3072 + 1024 + h * 64;
            const float* vp = kp + 1024;
#pragma unroll
            for (int i = 0; i < 4; i++) {
                int c = lc + i * 4;
                float4 kv = *(const float4*)(kp + c);
                Ks[lr * 65 + c]     = kv.x; Ks[lr * 65 + c + 1] = kv.y;
                Ks[lr * 65 + c + 2] = kv.z; Ks[lr * 65 + c + 3] = kv.w;
                float4 vv = *(const float4*)(vp + c);
                Vs[lr * 65 + c]     = vv.x; Vs[lr * 65 + c + 1] = vv.y;
                Vs[lr * 65 + c + 2] = vv.z; Vs[lr * 65 + c + 3] = vv.w;
            }
        }
        __syncthreads();

        float sc[16];
#pragma unroll
        for (int jt = 0; jt < 16; jt++) sc[jt] = 0.f;
#pragma unroll
        for (int d = 0; d < 64; d++) {
            float qd = Qs[row * 65 + d];
#pragma unroll
            for (int jt = 0; jt < 16; jt++)
                sc[jt] += qd * Ks[(sub * 16 + jt) * 65 + d];
        }
        float lm = -1e30f;
#pragma unroll
        for (int jt = 0; jt < 16; jt++) { sc[jt] *= 0.125f; lm = fmaxf(lm, sc[jt]); }
        lm = fmaxf(lm, __shfl_xor_sync(0xffffffffu, lm, 1));
        lm = fmaxf(lm, __shfl_xor_sync(0xffffffffu, lm, 2));
        float mn = fmaxf(m, lm);
        float alpha = __expf(m - mn);
        l *= alpha;
#pragma unroll
        for (int d = 0; d < 64; d++) acc[d] *= alpha;
#pragma unroll
        for (int jt = 0; jt < 16; jt++) {
            int j = sub * 16 + jt;
            float p = __expf(sc[jt] - mn);
            l += p;
#pragma unroll
            for (int d = 0; d < 64; d++) acc[d] += p * Vs[j * 65 + d];
        }
        m = mn;
    }

    // reduce 4 sub-threads per row
    l += __shfl_xor_sync(0xffffffffu, l, 1);
    l += __shfl_xor_sync(0xffffffffu, l, 2);
#pragma unroll
    for (int d = 0; d < 64; d++) {
        acc[d] += __shfl_xor_sync(0xffffffffu, acc[d], 1);
        acc[d] += __shfl_xor_sync(0xffffffffu, acc[d], 2);
    }
    float inv = 1.f / l;
    int t = tbase + qt * 64 + row;
#pragma unroll
    for (int i = 0; i < 16; i++) {
        int d = sub * 16 + i;
        g_ctx[(size_t)t * H_DIM + h * 64 + d] = acc[d] * inv;
    }
}

// ---------------- block reduce helper ----------------
__device__ __forceinline__ float blockReduceSum(float v)
{
    __shared__ float red[8];
    int lane = threadIdx.x & 31, warp = threadIdx.x >> 5;
#pragma unroll
    for (int o = 16; o; o >>= 1) v += __shfl_xor_sync(0xffffffffu, v, o);
    if (lane == 0) red[warp] = v;
    __syncthreads();
    if (warp == 0) {
        float t = (lane < 8) ? red[lane] : 0.f;
#pragma unroll
        for (int o = 4; o; o >>= 1) t += __shfl_xor_sync(0xffffffffu, t, o);
        if (lane == 0) red[0] = t;
    }
    __syncthreads();
    return red[0];
}

// ---------------- residual add + rmsnorm: hs = rmsnorm(a+b) ----------------
__global__ __launch_bounds__(256) void addnorm_kernel(
    const float* __restrict__ a, const float* __restrict__ b, float* __restrict__ out)
{
    int t = blockIdx.x, tx = threadIdx.x;
    const float* ap = a + (size_t)t * H_DIM;
    const float* bp = b + (size_t)t * H_DIM;
    float v[4]; float ss = 0.f;
#pragma unroll
    for (int j = 0; j < 4; j++) {
        int i = tx + j * 256;
        float x = ap[i] + bp[i];
        v[j] = x; ss += x * x;
    }
    float tot = blockReduceSum(ss);
    float scale = rsqrtf(tot * (1.f / H_DIM) + 1e-5f);
    float* op = out + (size_t)t * H_DIM;
#pragma unroll
    for (int j = 0; j < 4; j++) op[tx + j * 256] = v[j] * scale;
}

// ---------------- routing ----------------
__global__ void zerocnt_kernel() { if (threadIdx.x < NEXP) g_cnt[threadIdx.x] = 0; }

__global__ void route_kernel(const float* __restrict__ wg)
{
    int t = blockIdx.x, lane = threadIdx.x;     // 32 threads
    float p[8];
#pragma unroll
    for (int e = 0; e < 8; e++) p[e] = 0.f;
    const float* x = g_hs + (size_t)t * H_DIM;
    for (int h = lane; h < H_DIM; h += 32) {
        float xv = x[h];
#pragma unroll
        for (int e = 0; e < 8; e++) p[e] += xv * wg[h * 8 + e];
    }
#pragma unroll
    for (int e = 0; e < 8; e++)
#pragma unroll
        for (int o = 16; o; o >>= 1) p[e] += __shfl_xor_sync(0xffffffffu, p[e], o);

    if (lane == 0) {
        int e0 = 0; float l0 = p[0];
        for (int e = 1; e < 8; e++) if (p[e] > l0) { l0 = p[e]; e0 = e; }
        int e1 = -1; float l1 = -1e30f;
        for (int e = 0; e < 8; e++) if (e != e0 && p[e] > l1) { l1 = p[e]; e1 = e; }
        float w0 = 1.f / (1.f + expf(l1 - l0));   // = softmax-topk renormalized
        float w1 = 1.f - w0;
        int pos0 = atomicAdd(&g_cnt[e0], 1);
        g_rows[e0 * T_TOK + pos0] = t * 2;
        g_pairw[t * 2] = w0;
        int pos1 = atomicAdd(&g_cnt[e1], 1);
        g_rows[e1 * T_TOK + pos1] = t * 2 + 1;
        g_pairw[t * 2 + 1] = w1;
    }
}

// ---------------- MoE gate_up: act[pid, j] = silu(x@Wg) * (x@Wu) ----------------
__global__ __launch_bounds__(256) void moe_gateup_kernel(const float* __restrict__ w)
{
    int e = blockIdx.z;
    int count = g_cnt[e];
    int mBase = blockIdx.y * 128;
    if (mBase >= count) return;
    int nBase = blockIdx.x * 64;

    __shared__ float As[16][128];
    __shared__ float Bg[16][64];
    __shared__ float Bu[16][64];
    __shared__ int   sPid[128];

    int tx = threadIdx.x;
    if (tx < 128) {
        int r = mBase + tx;
        sPid[tx] = (r < count) ? g_rows[e * T_TOK + r] : -1;
    }
    __syncthreads();

    const float* We = w + (size_t)e * H_DIM * (2 * INTER);
    int ar = tx >> 1, ak = (tx & 1) * 8;
    int br = tx >> 4, bc = (tx & 15) * 4;
    int tr = tx >> 4, tc = tx & 15;
    int pidA = sPid[ar];
    const float* Arow = (pidA >= 0) ? (g_hs + (size_t)(pidA >> 1) * H_DIM) : g_hs;
    bool valid = pidA >= 0;

    float accG[8][4], accU[8][4];
#pragma unroll
    for (int i = 0; i < 8; i++)
#pragma unroll
        for (int j = 0; j < 4; j++) { accG[i][j] = 0.f; accU[i][j] = 0.f; }

    for (int kk = 0; kk < H_DIM; kk += 16) {
        float4 a0, a1;
        if (valid) { a0 = *(const float4*)(Arow + kk + ak); a1 = *(const float4*)(Arow + kk + ak + 4); }
        else       { a0 = make_float4(0,0,0,0); a1 = a0; }
        As[ak + 0][ar] = a0.x; As[ak + 1][ar] = a0.y; As[ak + 2][ar] = a0.z; As[ak + 3][ar] = a0.w;
        As[ak + 4][ar] = a1.x; As[ak + 5][ar] = a1.y; As[ak + 6][ar] = a1.z; As[ak + 7][ar] = a1.w;
        const float* bp = We + (size_t)(kk + br) * (2 * INTER) + nBase + bc;
        *(float4*)&Bg[br][bc] = *(const float4*)bp;
        *(float4*)&Bu[br][bc] = *(const float4*)(bp + INTER);
        __syncthreads();
#pragma unroll
        for (int k = 0; k < 16; k++) {
            float a[8], gb[4], ub[4];
#pragma unroll
            for (int i = 0; i < 8; i++) a[i] = As[k][tr * 8 + i];
#pragma unroll
            for (int j = 0; j < 4; j++) { gb[j] = Bg[k][tc * 4 + j]; ub[j] = Bu[k][tc * 4 + j]; }
#pragma unroll
            for (int i = 0; i < 8; i++)
#pragma unroll
                for (int j = 0; j < 4; j++) { accG[i][j] += a[i] * gb[j]; accU[i][j] += a[i] * ub[j]; }
        }
        __syncthreads();
    }
#pragma unroll
    for (int i = 0; i < 8; i++) {
        int pid = sPid[tr * 8 + i];
        if (pid >= 0) {
            float* dst = g_act + (size_t)pid * INTER + nBase + tc * 4;
#pragma unroll
            for (int j = 0; j < 4; j++) {
                float gv = accG[i][j];
                float sg = gv / (1.f + __expf(-gv));
                dst[j] = sg * accU[i][j];
            }
        }
    }
}

// ---------------- MoE down: ypair[pid,:] = w_pid * (act[pid] @ Wd[e]) ----------------
__global__ __launch_bounds__(256) void moe_down_kernel(const float* __restrict__ wd)
{
    int e = blockIdx.z;
    int count = g_cnt[e];
    int mBase = blockIdx.y * 128;
    if (mBase >= count) return;
    int nBase = blockIdx.x * 64;

    __shared__ float As[16][128];
    __shared__ float Bs[16][64];
    __shared__ int   sPid[128];

    int tx = threadIdx.x;
    if (tx < 128) {
        int r = mBase + tx;
        sPid[tx] = (r < count) ? g_rows[e * T_TOK + r] : -1;
    }
    __syncthreads();

    const float* We = wd + (size_t)e * INTER * H_DIM;
    int ar = tx >> 1, ak = (tx & 1) * 8;
    int br = tx >> 4, bc = (tx & 15) * 4;
    int tr = tx >> 4, tc = tx & 15;
    int pidA = sPid[ar];
    const float* Arow = (pidA >= 0) ? (g_act + (size_t)pidA * INTER) : g_act;
    bool valid = pidA >= 0;

    float acc[8][4];
#pragma unroll
    for (int i = 0; i < 8; i++)
#pragma unroll
        for (int j = 0; j < 4; j++) acc[i][j] = 0.f;

    for (int kk = 0; kk < INTER; kk += 16) {
        float4 a0, a1;
        if (valid) { a0 = *(const float4*)(Arow + kk + ak); a1 = *(const float4*)(Arow + kk + ak + 4); }
        else       { a0 = make_float4(0,0,0,0); a1 = a0; }
        As[ak + 0][ar] = a0.x; As[ak + 1][ar] = a0.y; As[ak + 2][ar] = a0.z; As[ak + 3][ar] = a0.w;
        As[ak + 4][ar] = a1.x; As[ak + 5][ar] = a1.y; As[ak + 6][ar] = a1.z; As[ak + 7][ar] = a1.w;
        *(float4*)&Bs[br][bc] = *(const float4*)(We + (size_t)(kk + br) * H_DIM + nBase + bc);
        __syncthreads();
#pragma unroll
        for (int k = 0; k < 16; k++) {
            float a[8], b[4];
#pragma unroll
            for (int i = 0; i < 8; i++) a[i] = As[k][tr * 8 + i];
#pragma unroll
            for (int j = 0; j < 4; j++) b[j] = Bs[k][tc * 4 + j];
#pragma unroll
            for (int i = 0; i < 8; i++)
#pragma unroll
                for (int j = 0; j < 4; j++) acc[i][j] += a[i] * b[j];
        }
        __syncthreads();
    }
#pragma unroll
    for (int i = 0; i < 8; i++) {
        int pid = sPid[tr * 8 + i];
        if (pid >= 0) {
            float wgt = g_pairw[pid];
            float* dst = g_ypair + (size_t)pid * H_DIM + nBase + tc * 4;
#pragma unroll
            for (int j = 0; j < 4; j++) dst[j] = wgt * acc[i][j];
        }
    }
}

// ---------------- final: out = rmsnorm(hs + y0 + y1) ----------------
__global__ __launch_bounds__(256) void final_kernel(float* __restrict__ out)
{
    int t = blockIdx.x, tx = threadIdx.x;
    const float* hs = g_hs + (size_t)t * H_DIM;
    const float* y0 = g_ypair + (size_t)(t * 2) * H_DIM;
    const float* y1 = y0 + H_DIM;
    float v[4]; float ss = 0.f;
#pragma unroll
    for (int j = 0; j < 4; j++) {
        int i = tx + j * 256;
        float x = hs[i] + y0[i] + y1[i];
        v[j] = x; ss += x * x;
    }
    float tot = blockReduceSum(ss);
    float scale = rsqrtf(tot * (1.f / H_DIM) + 1e-5f);
    float* op = out + (size_t)t * H_DIM;
#pragma unroll
    for (int j = 0; j < 4; j++) op[tx + j * 256] = v[j] * scale;
}

// ---------------- launch ----------------
extern "C" void kernel_launch(void* const* d_in, const int* in_sizes, int n_in,
                              void* d_out, int out_size)
{
    const float* hidden = (const float*)d_in[0];
    const float* cosp   = (const float*)d_in[1];
    const float* sinp   = (const float*)d_in[2];
    const float* w_qkv  = (const float*)d_in[3];
    const float* w_o    = (const float*)d_in[4];
    const float* w_gate = (const float*)d_in[5];
    const float* w_gu   = (const float*)d_in[6];
    const float* w_down = (const float*)d_in[7];
    float* out = (float*)d_out;

    float* qkv_ptr; cudaGetSymbolAddress((void**)&qkv_ptr, g_qkv);
    float* ctx_ptr; cudaGetSymbolAddress((void**)&ctx_ptr, g_ctx);
    float* tmp_ptr; cudaGetSymbolAddress((void**)&tmp_ptr, g_tmp);
    float* hs_ptr;  cudaGetSymbolAddress((void**)&hs_ptr,  g_hs);

    // 1. QKV projection: [2048,1024] x [1024,3072]
    sgemm_kernel<<<dim3(3072 / 64, 2048 / 128), 256>>>(hidden, w_qkv, qkv_ptr, 2048, 3072, 1024);

    // 2. RoPE in-place on q,k
    rope_kernel<<<(T_TOK * NHEAD * 32) / 256, 256>>>(cosp, sinp);

    // 3. attention
    cudaFuncSetAttribute(attn_kernel, cudaFuncAttributeMaxDynamicSharedMemorySize, 3 * 64 * 65 * 4);
    attn_kernel<<<dim3(16, 16, 2), 256, 3 * 64 * 65 * 4>>>();

    // 4. O projection
    sgemm_kernel<<<dim3(1024 / 64, 2048 / 128), 256>>>(ctx_ptr, w_o, tmp_ptr, 2048, 1024, 1024);

    // 5. hs = rmsnorm(x + attn_out)
    addnorm_kernel<<<T_TOK, 256>>>(hidden, tmp_ptr, hs_ptr);

    // 6. routing
    zerocnt_kernel<<<1, 32>>>();
    route_kernel<<<T_TOK, 32>>>(w_gate);

    // 7. expert gate_up + silu  (grid worst-case, early exit by count)
    moe_gateup_kernel<<<dim3(INTER / 64, 2048 / 128, NEXP), 256>>>(w_gu);

    // 8. expert down proj (weighted)
    moe_down_kernel<<<dim3(1024 / 64, 2048 / 128, NEXP), 256>>>(w_down);

    // 9. out = rmsnorm(hs + mixed)
    final_kernel<<<T_TOK, 256>>>(out);
}

// round 3
// speedup vs baseline: 1.0831x; 1.0827x over previous
#include <cuda_runtime.h>
#include <mma.h>
#include <math.h>

using namespace nvcuda;

// ---------------- problem constants ----------------
#define T_TOK 2048          // B*S
#define S_LEN 1024
#define H_DIM 1024
#define NHEAD 16
#define HD    64
#define NEXP  8
#define INTER 2816
#define GU2   (2*INTER)     // 5632

// ---------------- device scratch (no allocs allowed) ----------------
__device__ float g_qkv [(size_t)T_TOK * 3 * H_DIM];
__device__ float g_ctx [(size_t)T_TOK * H_DIM];
__device__ float g_tmp [(size_t)T_TOK * H_DIM];
__device__ float g_hs  [(size_t)T_TOK * H_DIM];
__device__ float g_gu  [(size_t)T_TOK * 2 * GU2];        // 92 MB: [4096, 5632]
__device__ float g_act [(size_t)T_TOK * 2 * INTER];      // 46 MB: [4096, 2816]
__device__ float g_ypair[(size_t)T_TOK * 2 * H_DIM];
__device__ float g_pairw[T_TOK * 2];
__device__ int   g_cnt [NEXP];
__device__ int   g_rows[NEXP * T_TOK];

// ================= TF32 wmma GEMM (plain): C[M,N]=A[M,K]@B[K,N] =================
// BM=128 BN=128 BK=16, 256 threads = 8 warps (4m x 2n), warp tile 32x64.
#define AS_LD 24
#define BS_LD 136

__global__ __launch_bounds__(256) void gemm_tf32_kernel(
    const float* __restrict__ A, const float* __restrict__ B,
    float* __restrict__ C, int M, int N, int K)
{
    __shared__ float As[128 * AS_LD];
    __shared__ float Bs[16 * BS_LD];

    int tx = threadIdx.x;
    int rowBase = blockIdx.y * 128;
    int colBase = blockIdx.x * 128;
    int warp = tx >> 5;
    int wm = warp >> 1, wn = warp & 1;

    wmma::fragment<wmma::accumulator, 16, 16, 8, float> c[2][4];
#pragma unroll
    for (int mi = 0; mi < 2; mi++)
#pragma unroll
        for (int ni = 0; ni < 4; ni++) wmma::fill_fragment(c[mi][ni], 0.f);

    int arow = tx >> 1, acol = (tx & 1) * 8;
    int brow = tx >> 4, bcol = (tx & 15) * 8;

    for (int kk = 0; kk < K; kk += 16) {
        const float* ap = A + (size_t)(rowBase + arow) * K + kk + acol;
        *(float4*)&As[arow * AS_LD + acol]     = *(const float4*)ap;
        *(float4*)&As[arow * AS_LD + acol + 4] = *(const float4*)(ap + 4);
        const float* bp = B + (size_t)(kk + brow) * N + colBase + bcol;
        *(float4*)&Bs[brow * BS_LD + bcol]     = *(const float4*)bp;
        *(float4*)&Bs[brow * BS_LD + bcol + 4] = *(const float4*)(bp + 4);
        __syncthreads();
#pragma unroll
        for (int ks = 0; ks < 2; ks++) {
            wmma::fragment<wmma::matrix_a, 16, 16, 8, wmma::precision::tf32, wmma::row_major> a[2];
            wmma::fragment<wmma::matrix_b, 16, 16, 8, wmma::precision::tf32, wmma::row_major> b[4];
#pragma unroll
            for (int mi = 0; mi < 2; mi++) {
                wmma::load_matrix_sync(a[mi], &As[(wm * 32 + mi * 16) * AS_LD + ks * 8], AS_LD);
#pragma unroll
                for (int i = 0; i < a[mi].num_elements; i++)
                    a[mi].x[i] = wmma::__float_to_tf32(a[mi].x[i]);
            }
#pragma unroll
            for (int ni = 0; ni < 4; ni++) {
                wmma::load_matrix_sync(b[ni], &Bs[(ks * 8) * BS_LD + wn * 64 + ni * 16], BS_LD);
#pragma unroll
                for (int i = 0; i < b[ni].num_elements; i++)
                    b[ni].x[i] = wmma::__float_to_tf32(b[ni].x[i]);
            }
#pragma unroll
            for (int mi = 0; mi < 2; mi++)
#pragma unroll
                for (int ni = 0; ni < 4; ni++)
                    wmma::mma_sync(c[mi][ni], a[mi], b[ni], c[mi][ni]);
        }
        __syncthreads();
    }
#pragma unroll
    for (int mi = 0; mi < 2; mi++)
#pragma unroll
        for (int ni = 0; ni < 4; ni++)
            wmma::store_matrix_sync(
                &C[(size_t)(rowBase + wm * 32 + mi * 16) * N + colBase + wn * 64 + ni * 16],
                c[mi][ni], N, wmma::mem_row_major);
}

// ============ TF32 wmma GEMM (gather rows / scatter rows, per expert) ============
// HALF_ROW: A row index = pid>>1 (gateup reads g_hs); else pid (down reads g_act).
// SCALE: multiply output rows by g_pairw[pid].
#define CS_LD 132
template<bool HALF_ROW, bool SCALE>
__global__ __launch_bounds__(256) void gemm_tf32_gather_kernel(
    const float* __restrict__ Abase, const float* __restrict__ Bbase,
    float* __restrict__ Cbase, int N, int K, size_t strideB, int ldA, int ldC)
{
    extern __shared__ float sm[];
    float* As = sm;                 // 128 x 24
    float* Bs = sm + 128 * AS_LD;   // 16 x 136
    float* Cs = sm;                 // reused in epilogue: 128 x 132
    __shared__ int sPid[128];

    int e = blockIdx.z;
    int count = g_cnt[e];
    int mBase = blockIdx.y * 128;
    if (mBase >= count) return;
    int colBase = blockIdx.x * 128;

    int tx = threadIdx.x;
    if (tx < 128) {
        int r = mBase + tx;
        sPid[tx] = (r < count) ? g_rows[e * T_TOK + r] : -1;
    }
    __syncthreads();

    const float* B = Bbase + (size_t)e * strideB;
    int warp = tx >> 5;
    int wm = warp >> 1, wn = warp & 1;

    wmma::fragment<wmma::accumulator, 16, 16, 8, float> c[2][4];
#pragma unroll
    for (int mi = 0; mi < 2; mi++)
#pragma unroll
        for (int ni = 0; ni < 4; ni++) wmma::fill_fragment(c[mi][ni], 0.f);

    int arow = tx >> 1, acol = (tx & 1) * 8;
    int brow = tx >> 4, bcol = (tx & 15) * 8;
    int pidA = sPid[arow];
    const float* Arow = Abase;
    bool valid = (pidA >= 0);
    if (valid) Arow = Abase + (size_t)(HALF_ROW ? (pidA >> 1) : pidA) * ldA;

    for (int kk = 0; kk < K; kk += 16) {
        float4 a0, a1;
        if (valid) { a0 = *(const float4*)(Arow + kk + acol); a1 = *(const float4*)(Arow + kk + acol + 4); }
        else       { a0 = make_float4(0,0,0,0); a1 = a0; }
        *(float4*)&As[arow * AS_LD + acol]     = a0;
        *(float4*)&As[arow * AS_LD + acol + 4] = a1;
        const float* bp = B + (size_t)(kk + brow) * N + colBase + bcol;
        *(float4*)&Bs[brow * BS_LD + bcol]     = *(const float4*)bp;
        *(float4*)&Bs[brow * BS_LD + bcol + 4] = *(const float4*)(bp + 4);
        __syncthreads();
#pragma unroll
        for (int ks = 0; ks < 2; ks++) {
            wmma::fragment<wmma::matrix_a, 16, 16, 8, wmma::precision::tf32, wmma::row_major> a[2];
            wmma::fragment<wmma::matrix_b, 16, 16, 8, wmma::precision::tf32, wmma::row_major> b[4];
#pragma unroll
            for (int mi = 0; mi < 2; mi++) {
                wmma::load_matrix_sync(a[mi], &As[(wm * 32 + mi * 16) * AS_LD + ks * 8], AS_LD);
#pragma unroll
                for (int i = 0; i < a[mi].num_elements; i++)
                    a[mi].x[i] = wmma::__float_to_tf32(a[mi].x[i]);
            }
#pragma unroll
            for (int ni = 0; ni < 4; ni++) {
                wmma::load_matrix_sync(b[ni], &Bs[(ks * 8) * BS_LD + wn * 64 + ni * 16], BS_LD);
#pragma unroll
                for (int i = 0; i < b[ni].num_elements; i++)
                    b[ni].x[i] = wmma::__float_to_tf32(b[ni].x[i]);
            }
#pragma unroll
            for (int mi = 0; mi < 2; mi++)
#pragma unroll
                for (int ni = 0; ni < 4; ni++)
                    wmma::mma_sync(c[mi][ni], a[mi], b[ni], c[mi][ni]);
        }
        __syncthreads();
    }

    // epilogue: stage into shared, then scatter rows by pid
#pragma unroll
    for (int mi = 0; mi < 2; mi++)
#pragma unroll
        for (int ni = 0; ni < 4; ni++)
            wmma::store_matrix_sync(&Cs[(wm * 32 + mi * 16) * CS_LD + wn * 64 + ni * 16],
                                    c[mi][ni], CS_LD, wmma::mem_row_major);
    __syncthreads();

    int orow = tx >> 1;
    int ocol = (tx & 1) * 64;
    int pid = sPid[orow];
    if (pid >= 0) {
        float scale = SCALE ? g_pairw[pid] : 1.f;
        float* dst = Cbase + (size_t)pid * ldC + colBase + ocol;
        const float* src = &Cs[orow * CS_LD + ocol];
#pragma unroll
        for (int i = 0; i < 16; i++) {
            float4 v = *(const float4*)(src + i * 4);
            v.x *= scale; v.y *= scale; v.z *= scale; v.w *= scale;
            *(float4*)(dst + i * 4) = v;
        }
    }
}

// ---------------- silu-mul: act[pid][j] = silu(gu[pid][j]) * gu[pid][j+INTER] ----------------
__global__ __launch_bounds__(256) void silu_kernel()
{
    size_t idx = ((size_t)blockIdx.x * blockDim.x + threadIdx.x) * 4;
    size_t total = (size_t)T_TOK * 2 * INTER;
    if (idx >= total) return;
    size_t pid = idx / INTER;
    size_t j = idx - pid * INTER;
    const float* gp = g_gu + pid * GU2 + j;
    float4 g = *(const float4*)gp;
    float4 u = *(const float4*)(gp + INTER);
    float4 r;
    r.x = g.x / (1.f + __expf(-g.x)) * u.x;
    r.y = g.y / (1.f + __expf(-g.y)) * u.y;
    r.z = g.z / (1.f + __expf(-g.z)) * u.z;
    r.w = g.w / (1.f + __expf(-g.w)) * u.w;
    *(float4*)(g_act + idx) = r;
}

// ---------------- RoPE (in-place on q,k inside g_qkv) ----------------
__global__ void rope_kernel(const float* __restrict__ cosp, const float* __restrict__ sinp)
{
    int idx = blockIdx.x * blockDim.x + threadIdx.x;
    if (idx >= T_TOK * NHEAD * 32) return;
    int d = idx & 31;
    int n = (idx >> 5) & 15;
    int t = idx >> 9;
    int s = t & (S_LEN - 1);
    float c1 = cosp[s * 64 + d],      s1 = sinp[s * 64 + d];
    float c2 = cosp[s * 64 + d + 32], s2 = sinp[s * 64 + d + 32];
    size_t base = (size_t)t * 3072 + n * 64 + d;
    float x1 = g_qkv[base], x2 = g_qkv[base + 32];
    g_qkv[base]      = x1 * c1 - x2 * s1;
    g_qkv[base + 32] = x2 * c2 + x1 * s2;
    base += 1024;
    x1 = g_qkv[base]; x2 = g_qkv[base + 32];
    g_qkv[base]      = x1 * c1 - x2 * s1;
    g_qkv[base + 32] = x2 * c2 + x1 * s2;
}

// ---------------- attention: flash-style, one block per (b,h,qtile64) ----------------
__global__ __launch_bounds__(256) void attn_kernel()
{
    extern __shared__ float sm[];
    float* Qs = sm;
    float* Ks = sm + 64 * 65;
    float* Vs = sm + 2 * 64 * 65;

    int qt = blockIdx.x, h = blockIdx.y, b = blockIdx.z;
    int tx = threadIdx.x;
    int row = tx >> 2, sub = tx & 3;
    int tbase = b * S_LEN;

    {
        int lr = tx >> 2, lc = (tx & 3) * 16;
        const float* qp = g_qkv + (size_t)(tbase + qt * 64 + lr) * 3072 + h * 64;
#pragma unroll
        for (int i = 0; i < 4; i++) {
            int c = lc + i * 4;
            float4 v = *(const float4*)(qp + c);
            Qs[lr * 65 + c]     = v.x; Qs[lr * 65 + c + 1] = v.y;
            Qs[lr * 65 + c + 2] = v.z; Qs[lr * 65 + c + 3] = v.w;
        }
    }

    float acc[64];
#pragma unroll
    for (int i = 0; i < 64; i++) acc[i] = 0.f;
    float m = -1e30f, l = 0.f;

    for (int kt = 0; kt < 16; kt++) {
        __syncthreads();
        {
            int lr = tx >> 2, lc = (tx & 3) * 16;
            const float* kp = g_qkv + (size_t)(tbase + kt * 64 + lr) * 3072 + 1024 + h * 64;
            const float* vp = kp + 1024;
#pragma unroll
            for (int i = 0; i < 4; i++) {
                int c = lc + i * 4;
                float4 kv = *(const float4*)(kp + c);
                Ks[lr * 65 + c]     = kv.x; Ks[lr * 65 + c + 1] = kv.y;
                Ks[lr * 65 + c + 2] = kv.z; Ks[lr * 65 + c + 3] = kv.w;
                float4 vv = *(const float4*)(vp + c);
                Vs[lr * 65 + c]     = vv.x; Vs[lr * 65 + c + 1] = vv.y;
                Vs[lr * 65 + c + 2] = vv.z; Vs[lr * 65 + c + 3] = vv.w;
            }
        }
        __syncthreads();

        float sc[16];
#pragma unroll
        for (int jt = 0; jt < 16; jt++) sc[jt] = 0.f;
#pragma unroll
        for (int d = 0; d < 64; d++) {
            float qd = Qs[row * 65 + d];
#pragma unroll
            for (int jt = 0; jt < 16; jt++)
                sc[jt] += qd * Ks[(sub * 16 + jt) * 65 + d];
        }
        float lm = -1e30f;
#pragma unroll
        for (int jt = 0; jt < 16; jt++) { sc[jt] *= 0.125f; lm = fmaxf(lm, sc[jt]); }
        lm = fmaxf(lm, __shfl_xor_sync(0xffffffffu, lm, 1));
        lm = fmaxf(lm, __shfl_xor_sync(0xffffffffu, lm, 2));
        float mn = fmaxf(m, lm);
        float alpha = __expf(m - mn);
        l *= alpha;
#pragma unroll
        for (int d = 0; d < 64; d++) acc[d] *= alpha;
#pragma unroll
        for (int jt = 0; jt < 16; jt++) {
            int j = sub * 16 + jt;
            float p = __expf(sc[jt] - mn);
            l += p;
#pragma unroll
            for (int d = 0; d < 64; d++) acc[d] += p * Vs[j * 65 + d];
        }
        m = mn;
    }

    l += __shfl_xor_sync(0xffffffffu, l, 1);
    l += __shfl_xor_sync(0xffffffffu, l, 2);
#pragma unroll
    for (int d = 0; d < 64; d++) {
        acc[d] += __shfl_xor_sync(0xffffffffu, acc[d], 1);
        acc[d] += __shfl_xor_sync(0xffffffffu, acc[d], 2);
    }
    float inv = 1.f / l;
    int t = tbase + qt * 64 + row;
#pragma unroll
    for (int i = 0; i < 16; i++) {
        int d = sub * 16 + i;
        g_ctx[(size_t)t * H_DIM + h * 64 + d] = acc[d] * inv;
    }
}

// ---------------- block reduce helper ----------------
__device__ __forceinline__ float blockReduceSum(float v)
{
    __shared__ float red[8];
    int lane = threadIdx.x & 31, warp = threadIdx.x >> 5;
#pragma unroll
    for (int o = 16; o; o >>= 1) v += __shfl_xor_sync(0xffffffffu, v, o);
    if (lane == 0) red[warp] = v;
    __syncthreads();
    if (warp == 0) {
        float t = (lane < 8) ? red[lane] : 0.f;
#pragma unroll
        for (int o = 4; o; o >>= 1) t += __shfl_xor_sync(0xffffffffu, t, o);
        if (lane == 0) red[0] = t;
    }
    __syncthreads();
    return red[0];
}

// ---------------- residual add + rmsnorm ----------------
__global__ __launch_bounds__(256) void addnorm_kernel(
    const float* __restrict__ a, const float* __restrict__ b, float* __restrict__ out)
{
    int t = blockIdx.x, tx = threadIdx.x;
    const float* ap = a + (size_t)t * H_DIM;
    const float* bp = b + (size_t)t * H_DIM;
    float v[4]; float ss = 0.f;
#pragma unroll
    for (int j = 0; j < 4; j++) {
        int i = tx + j * 256;
        float x = ap[i] + bp[i];
        v[j] = x; ss += x * x;
    }
    float tot = blockReduceSum(ss);
    float scale = rsqrtf(tot * (1.f / H_DIM) + 1e-5f);
    float* op = out + (size_t)t * H_DIM;
#pragma unroll
    for (int j = 0; j < 4; j++) op[tx + j * 256] = v[j] * scale;
}

// ---------------- routing ----------------
__global__ void zerocnt_kernel() { if (threadIdx.x < NEXP) g_cnt[threadIdx.x] = 0; }

__global__ void route_kernel(const float* __restrict__ wg)
{
    int t = blockIdx.x, lane = threadIdx.x;
    float p[8];
#pragma unroll
    for (int e = 0; e < 8; e++) p[e] = 0.f;
    const float* x = g_hs + (size_t)t * H_DIM;
    for (int h = lane; h < H_DIM; h += 32) {
        float xv = x[h];
#pragma unroll
        for (int e = 0; e < 8; e++) p[e] += xv * wg[h * 8 + e];
    }
#pragma unroll
    for (int e = 0; e < 8; e++)
#pragma unroll
        for (int o = 16; o; o >>= 1) p[e] += __shfl_xor_sync(0xffffffffu, p[e], o);

    if (lane == 0) {
        int e0 = 0; float l0 = p[0];
        for (int e = 1; e < 8; e++) if (p[e] > l0) { l0 = p[e]; e0 = e; }
        int e1 = -1; float l1 = -1e30f;
        for (int e = 0; e < 8; e++) if (e != e0 && p[e] > l1) { l1 = p[e]; e1 = e; }
        float w0 = 1.f / (1.f + expf(l1 - l0));
        float w1 = 1.f - w0;
        int pos0 = atomicAdd(&g_cnt[e0], 1);
        g_rows[e0 * T_TOK + pos0] = t * 2;
        g_pairw[t * 2] = w0;
        int pos1 = atomicAdd(&g_cnt[e1], 1);
        g_rows[e1 * T_TOK + pos1] = t * 2 + 1;
        g_pairw[t * 2 + 1] = w1;
    }
}

// ---------------- final: out = rmsnorm(hs + y0 + y1) ----------------
__global__ __launch_bounds__(256) void final_kernel(float* __restrict__ out)
{
    int t = blockIdx.x, tx = threadIdx.x;
    const float* hs = g_hs + (size_t)t * H_DIM;
    const float* y0 = g_ypair + (size_t)(t * 2) * H_DIM;
    const float* y1 = y0 + H_DIM;
    float v[4]; float ss = 0.f;
#pragma unroll
    for (int j = 0; j < 4; j++) {
        int i = tx + j * 256;
        float x = hs[i] + y0[i] + y1[i];
        v[j] = x; ss += x * x;
    }
    float tot = blockReduceSum(ss);
    float scale = rsqrtf(tot * (1.f / H_DIM) + 1e-5f);
    float* op = out + (size_t)t * H_DIM;
#pragma unroll
    for (int j = 0; j < 4; j++) op[tx + j * 256] = v[j] * scale;
}

// ---------------- launch ----------------
extern "C" void kernel_launch(void* const* d_in, const int* in_sizes, int n_in,
                              void* d_out, int out_size)
{
    const float* hidden = (const float*)d_in[0];
    const float* cosp   = (const float*)d_in[1];
    const float* sinp   = (const float*)d_in[2];
    const float* w_qkv  = (const float*)d_in[3];
    const float* w_o    = (const float*)d_in[4];
    const float* w_gate = (const float*)d_in[5];
    const float* w_gu   = (const float*)d_in[6];
    const float* w_down = (const float*)d_in[7];
    float* out = (float*)d_out;

    float* qkv_ptr; cudaGetSymbolAddress((void**)&qkv_ptr, g_qkv);
    float* ctx_ptr; cudaGetSymbolAddress((void**)&ctx_ptr, g_ctx);
    float* tmp_ptr; cudaGetSymbolAddress((void**)&tmp_ptr, g_tmp);
    float* hs_ptr;  cudaGetSymbolAddress((void**)&hs_ptr,  g_hs);
    float* gu_ptr;  cudaGetSymbolAddress((void**)&gu_ptr,  g_gu);
    float* act_ptr; cudaGetSymbolAddress((void**)&act_ptr, g_act);
    float* yp_ptr;  cudaGetSymbolAddress((void**)&yp_ptr,  g_ypair);

    static bool attrs_set = false;
    const int GATHER_SMEM = 128 * CS_LD * 4;  // 67.6 KB (epilogue reuses load smem)
    if (!attrs_set) {
        cudaFuncSetAttribute(attn_kernel, cudaFuncAttributeMaxDynamicSharedMemorySize, 3 * 64 * 65 * 4);
        cudaFuncSetAttribute(gemm_tf32_gather_kernel<true,  false>,
                             cudaFuncAttributeMaxDynamicSharedMemorySize, GATHER_SMEM);
        cudaFuncSetAttribute(gemm_tf32_gather_kernel<false, true>,
                             cudaFuncAttributeMaxDynamicSharedMemorySize, GATHER_SMEM);
        attrs_set = true;
    }

    // 1. QKV projection: [2048,1024] x [1024,3072]
    gemm_tf32_kernel<<<dim3(3072 / 128, 2048 / 128), 256>>>(hidden, w_qkv, qkv_ptr, 2048, 3072, 1024);

    // 2. RoPE in-place on q,k
    rope_kernel<<<(T_TOK * NHEAD * 32) / 256, 256>>>(cosp, sinp);

    // 3. attention
    attn_kernel<<<dim3(16, 16, 2), 256, 3 * 64 * 65 * 4>>>();

    // 4. O projection
    gemm_tf32_kernel<<<dim3(1024 / 128, 2048 / 128), 256>>>(ctx_ptr, w_o, tmp_ptr, 2048, 1024, 1024);

    // 5. hs = rmsnorm(x + attn_out)
    addnorm_kernel<<<T_TOK, 256>>>(hidden, tmp_ptr, hs_ptr);

    // 6. routing
    zerocnt_kernel<<<1, 32>>>();
    route_kernel<<<T_TOK, 32>>>(w_gate);

    // 7. expert gate_up GEMM into g_gu  (A = g_hs rows pid>>1, N = 5632)
    gemm_tf32_gather_kernel<true, false><<<dim3(GU2 / 128, 2048 / 128, NEXP), 256, GATHER_SMEM>>>(
        hs_ptr, w_gu, gu_ptr, GU2, H_DIM, (size_t)H_DIM * GU2, H_DIM, GU2);

    // 8. silu-mul: g_act = silu(gate) * up
    {
        size_t total = (size_t)T_TOK * 2 * INTER / 4;
        silu_kernel<<<(unsigned)((total + 255) / 256), 256>>>();
    }

    // 9. expert down proj (weighted, A = g_act rows pid, N = 1024)
    gemm_tf32_gather_kernel<false, true><<<dim3(1024 / 128, 2048 / 128, NEXP), 256, GATHER_SMEM>>>(
        act_ptr, w_down, yp_ptr, H_DIM, INTER, (size_t)INTER * H_DIM, INTER, H_DIM);

    // 10. out = rmsnorm(hs + mixed)
    final_kernel<<<T_TOK, 256>>>(out);
}

// round 5
// speedup vs baseline: 1.3037x; 1.2036x over previous
#include <cuda_runtime.h>
#include <mma.h>
#include <math.h>
#include <cstdint>

using namespace nvcuda;

// ---------------- problem constants ----------------
#define T_TOK 2048
#define S_LEN 1024
#define H_DIM 1024
#define NHEAD 16
#define HD    64
#define NEXP  8
#define INTER 2816
#define GU2   (2*INTER)

// ---------------- device scratch ----------------
__device__ float g_qkv [(size_t)T_TOK * 3 * H_DIM];
__device__ float g_ctx [(size_t)T_TOK * H_DIM];
__device__ float g_tmp [(size_t)T_TOK * H_DIM];
__device__ float g_hs  [(size_t)T_TOK * H_DIM];
__device__ float g_act [(size_t)T_TOK * 2 * INTER];
__device__ float g_ypair[(size_t)T_TOK * 2 * H_DIM];
__device__ float g_pairw[T_TOK * 2];
__device__ int   g_cnt [NEXP];
__device__ int   g_rows[NEXP * T_TOK];

// ---------------- cp.async helpers ----------------
__device__ __forceinline__ void cp16(float* s, const float* g, bool pred) {
    unsigned int sa = (unsigned int)__cvta_generic_to_shared(s);
    int sz = pred ? 16 : 0;
    asm volatile("cp.async.cg.shared.global [%0], [%1], 16, %2;\n" :: "r"(sa), "l"(g), "r"(sz));
}
__device__ __forceinline__ void cp_commit() { asm volatile("cp.async.commit_group;\n"); }
__device__ __forceinline__ void cp_wait1()  { asm volatile("cp.async.wait_group 1;\n" ::: "memory"); }
__device__ __forceinline__ void cp_wait0()  { asm volatile("cp.async.wait_group 0;\n" ::: "memory"); }

#define AS_LD 24
#define BS_LD 136
#define CS_LD 132

// fragment typedefs
typedef wmma::fragment<wmma::matrix_a, 16, 16, 8, wmma::precision::tf32, wmma::row_major> FragA;
typedef wmma::fragment<wmma::matrix_b, 16, 16, 8, wmma::precision::tf32, wmma::row_major> FragB;
typedef wmma::fragment<wmma::accumulator, 16, 16, 8, float> FragC;

__device__ __forceinline__ void load_a_frags(FragA a[2], const float* As, int wm, int ks) {
#pragma unroll
    for (int mi = 0; mi < 2; mi++) {
        wmma::load_matrix_sync(a[mi], &As[(wm * 32 + mi * 16) * AS_LD + ks * 8], AS_LD);
#pragma unroll
        for (int i = 0; i < a[mi].num_elements; i++)
            a[mi].x[i] = wmma::__float_to_tf32(a[mi].x[i]);
    }
}
__device__ __forceinline__ void load_b_frags(FragB b[4], const float* Bs, int wn, int ks) {
#pragma unroll
    for (int ni = 0; ni < 4; ni++) {
        wmma::load_matrix_sync(b[ni], &Bs[(ks * 8) * BS_LD + wn * 64 + ni * 16], BS_LD);
#pragma unroll
        for (int i = 0; i < b[ni].num_elements; i++)
            b[ni].x[i] = wmma::__float_to_tf32(b[ni].x[i]);
    }
}

// ================= plain TF32 GEMM, 2-stage cp.async pipeline =================
__global__ __launch_bounds__(256) void gemm_tf32_kernel(
    const float* __restrict__ A, const float* __restrict__ B,
    float* __restrict__ C, int M, int N, int K)
{
    __shared__ float As[2][128 * AS_LD];
    __shared__ float Bs[2][16 * BS_LD];

    int tx = threadIdx.x;
    int rowBase = blockIdx.y * 128;
    int colBase = blockIdx.x * 128;
    int warp = tx >> 5, wm = warp >> 1, wn = warp & 1;

    FragC c[2][4];
#pragma unroll
    for (int mi = 0; mi < 2; mi++)
#pragma unroll
        for (int ni = 0; ni < 4; ni++) wmma::fill_fragment(c[mi][ni], 0.f);

    int arow = tx >> 1, acol = (tx & 1) * 8;
    int brow = tx >> 4, bcol = (tx & 15) * 8;
    const float* aP = A + (size_t)(rowBase + arow) * K + acol;
    const float* bP = B + (size_t)brow * N + colBase + bcol;
    int nt = K >> 4;

    cp16(&As[0][arow * AS_LD + acol],     aP,     true);
    cp16(&As[0][arow * AS_LD + acol + 4], aP + 4, true);
    cp16(&Bs[0][brow * BS_LD + bcol],     bP,     true);
    cp16(&Bs[0][brow * BS_LD + bcol + 4], bP + 4, true);
    cp_commit();

    for (int t = 0; t < nt; t++) {
        int cur = t & 1, nxt = cur ^ 1;
        if (t + 1 < nt) {
            const float* a2 = aP + (t + 1) * 16;
            const float* b2 = bP + (size_t)(t + 1) * 16 * N;
            cp16(&As[nxt][arow * AS_LD + acol],     a2,     true);
            cp16(&As[nxt][arow * AS_LD + acol + 4], a2 + 4, true);
            cp16(&Bs[nxt][brow * BS_LD + bcol],     b2,     true);
            cp16(&Bs[nxt][brow * BS_LD + bcol + 4], b2 + 4, true);
            cp_commit();
            cp_wait1();
        } else cp_wait0();
        __syncthreads();
#pragma unroll
        for (int ks = 0; ks < 2; ks++) {
            FragA a[2]; FragB b[4];
            load_a_frags(a, As[cur], wm, ks);
            load_b_frags(b, Bs[cur], wn, ks);
#pragma unroll
            for (int mi = 0; mi < 2; mi++)
#pragma unroll
                for (int ni = 0; ni < 4; ni++)
                    wmma::mma_sync(c[mi][ni], a[mi], b[ni], c[mi][ni]);
        }
        __syncthreads();
    }
#pragma unroll
    for (int mi = 0; mi < 2; mi++)
#pragma unroll
        for (int ni = 0; ni < 4; ni++)
            wmma::store_matrix_sync(
                &C[(size_t)(rowBase + wm * 32 + mi * 16) * N + colBase + wn * 64 + ni * 16],
                c[mi][ni], N, wmma::mem_row_major);
}

// ================= MoE gate_up fused silu: g_act[pid] = silu(x@Wg)*(x@Wu) =================
__global__ __launch_bounds__(256) void moe_gateup_kernel(const float* __restrict__ Wgu)
{
    extern __shared__ float sm[];
    float* As = sm;                         // 2 x 128 x 24
    float* Bg = sm + 2 * 128 * AS_LD;       // 2 x 16 x 136
    float* Bu = Bg + 2 * 16 * BS_LD;        // 2 x 16 x 136
    float* Cs = sm;                         // epilogue reuse: 128 x 132
    __shared__ int sPid[128];

    int e = blockIdx.z;
    int count = g_cnt[e];
    int mBase = blockIdx.y * 128;
    if (mBase >= count) return;
    int nBase = blockIdx.x * 128;           // within INTER

    int tx = threadIdx.x;
    if (tx < 128) {
        int r = mBase + tx;
        sPid[tx] = (r < count) ? g_rows[e * T_TOK + r] : -1;
    }
    __syncthreads();

    const float* B = Wgu + (size_t)e * H_DIM * GU2;
    int warp = tx >> 5, wm = warp >> 1, wn = warp & 1;

    FragC cg[2][4], cu[2][4];
#pragma unroll
    for (int mi = 0; mi < 2; mi++)
#pragma unroll
        for (int ni = 0; ni < 4; ni++) { wmma::fill_fragment(cg[mi][ni], 0.f); wmma::fill_fragment(cu[mi][ni], 0.f); }

    int arow = tx >> 1, acol = (tx & 1) * 8;
    int brow = tx >> 4, bcol = (tx & 15) * 8;
    int pidA = sPid[arow];
    bool valid = (pidA >= 0);
    const float* aP = g_hs + (valid ? (size_t)(pidA >> 1) * H_DIM : 0) + acol;
    const float* bgP = B + (size_t)brow * GU2 + nBase + bcol;
    const float* buP = bgP + INTER;
    const int nt = H_DIM >> 4;   // 64

    cp16(&As[0 * 128 * AS_LD + arow * AS_LD + acol],     aP,      valid);
    cp16(&As[0 * 128 * AS_LD + arow * AS_LD + acol + 4], aP + 4,  valid);
    cp16(&Bg[0 * 16 * BS_LD + brow * BS_LD + bcol],      bgP,     true);
    cp16(&Bg[0 * 16 * BS_LD + brow * BS_LD + bcol + 4],  bgP + 4, true);
    cp16(&Bu[0 * 16 * BS_LD + brow * BS_LD + bcol],      buP,     true);
    cp16(&Bu[0 * 16 * BS_LD + brow * BS_LD + bcol + 4],  buP + 4, true);
    cp_commit();

    for (int t = 0; t < nt; t++) {
        int cur = t & 1, nxt = cur ^ 1;
        if (t + 1 < nt) {
            const float* a2 = aP + (t + 1) * 16;
            const float* bg2 = bgP + (size_t)(t + 1) * 16 * GU2;
            const float* bu2 = buP + (size_t)(t + 1) * 16 * GU2;
            cp16(&As[nxt * 128 * AS_LD + arow * AS_LD + acol],     a2,      valid);
            cp16(&As[nxt * 128 * AS_LD + arow * AS_LD + acol + 4], a2 + 4,  valid);
            cp16(&Bg[nxt * 16 * BS_LD + brow * BS_LD + bcol],      bg2,     true);
            cp16(&Bg[nxt * 16 * BS_LD + brow * BS_LD + bcol + 4],  bg2 + 4, true);
            cp16(&Bu[nxt * 16 * BS_LD + brow * BS_LD + bcol],      bu2,     true);
            cp16(&Bu[nxt * 16 * BS_LD + brow * BS_LD + bcol + 4],  bu2 + 4, true);
            cp_commit();
            cp_wait1();
        } else cp_wait0();
        __syncthreads();
#pragma unroll
        for (int ks = 0; ks < 2; ks++) {
            FragA a[2]; FragB bg[4], bu[4];
            load_a_frags(a, &As[cur * 128 * AS_LD], wm, ks);
            load_b_frags(bg, &Bg[cur * 16 * BS_LD], wn, ks);
            load_b_frags(bu, &Bu[cur * 16 * BS_LD], wn, ks);
#pragma unroll
            for (int mi = 0; mi < 2; mi++)
#pragma unroll
                for (int ni = 0; ni < 4; ni++) {
                    wmma::mma_sync(cg[mi][ni], a[mi], bg[ni], cg[mi][ni]);
                    wmma::mma_sync(cu[mi][ni], a[mi], bu[ni], cu[mi][ni]);
                }
        }
        __syncthreads();
    }

    // fuse silu in-fragment, stage to shared, scatter rows
#pragma unroll
    for (int mi = 0; mi < 2; mi++)
#pragma unroll
        for (int ni = 0; ni < 4; ni++) {
#pragma unroll
            for (int i = 0; i < cg[mi][ni].num_elements; i++) {
                float g = cg[mi][ni].x[i];
                cg[mi][ni].x[i] = g / (1.f + __expf(-g)) * cu[mi][ni].x[i];
            }
            wmma::store_matrix_sync(&Cs[(wm * 32 + mi * 16) * CS_LD + wn * 64 + ni * 16],
                                    cg[mi][ni], CS_LD, wmma::mem_row_major);
        }
    __syncthreads();

    int orow = tx >> 1, ocol = (tx & 1) * 64;
    int pid = sPid[orow];
    if (pid >= 0) {
        float* dst = g_act + (size_t)pid * INTER + nBase + ocol;
        const float* src = &Cs[orow * CS_LD + ocol];
#pragma unroll
        for (int i = 0; i < 16; i++)
            *(float4*)(dst + i * 4) = *(const float4*)(src + i * 4);
    }
}

// ================= MoE down: ypair[pid] = pairw[pid] * (act[pid] @ Wd[e]) =================
__global__ __launch_bounds__(256) void moe_down_kernel(const float* __restrict__ Wd)
{
    extern __shared__ float sm[];
    float* As = sm;                      // 2 x 128 x 24
    float* Bs = sm + 2 * 128 * AS_LD;    // 2 x 16 x 136
    float* Cs = sm;                      // epilogue reuse
    __shared__ int sPid[128];

    int e = blockIdx.z;
    int count = g_cnt[e];
    int mBase = blockIdx.y * 128;
    if (mBase >= count) return;
    int colBase = blockIdx.x * 128;

    int tx = threadIdx.x;
    if (tx < 128) {
        int r = mBase + tx;
        sPid[tx] = (r < count) ? g_rows[e * T_TOK + r] : -1;
    }
    __syncthreads();

    const float* B = Wd + (size_t)e * INTER * H_DIM;
    int warp = tx >> 5, wm = warp >> 1, wn = warp & 1;

    FragC c[2][4];
#pragma unroll
    for (int mi = 0; mi < 2; mi++)
#pragma unroll
        for (int ni = 0; ni < 4; ni++) wmma::fill_fragment(c[mi][ni], 0.f);

    int arow = tx >> 1, acol = (tx & 1) * 8;
    int brow = tx >> 4, bcol = (tx & 15) * 8;
    int pidA = sPid[arow];
    bool valid = (pidA >= 0);
    const float* aP = g_act + (valid ? (size_t)pidA * INTER : 0) + acol;
    const float* bP = B + (size_t)brow * H_DIM + colBase + bcol;
    const int nt = INTER >> 4;   // 176

    cp16(&As[0 * 128 * AS_LD + arow * AS_LD + acol],     aP,     valid);
    cp16(&As[0 * 128 * AS_LD + arow * AS_LD + acol + 4], aP + 4, valid);
    cp16(&Bs[0 * 16 * BS_LD + brow * BS_LD + bcol],      bP,     true);
    cp16(&Bs[0 * 16 * BS_LD + brow * BS_LD + bcol + 4],  bP + 4, true);
    cp_commit();

    for (int t = 0; t < nt; t++) {
        int cur = t & 1, nxt = cur ^ 1;
        if (t + 1 < nt) {
            const float* a2 = aP + (t + 1) * 16;
            const float* b2 = bP + (size_t)(t + 1) * 16 * H_DIM;
            cp16(&As[nxt * 128 * AS_LD + arow * AS_LD + acol],     a2,     valid);
            cp16(&As[nxt * 128 * AS_LD + arow * AS_LD + acol + 4], a2 + 4, valid);
            cp16(&Bs[nxt * 16 * BS_LD + brow * BS_LD + bcol],      b2,     true);
            cp16(&Bs[nxt * 16 * BS_LD + brow * BS_LD + bcol + 4],  b2 + 4, true);
            cp_commit();
            cp_wait1();
        } else cp_wait0();
        __syncthreads();
#pragma unroll
        for (int ks = 0; ks < 2; ks++) {
            FragA a[2]; FragB b[4];
            load_a_frags(a, &As[cur * 128 * AS_LD], wm, ks);
            load_b_frags(b, &Bs[cur * 16 * BS_LD], wn, ks);
#pragma unroll
            for (int mi = 0; mi < 2; mi++)
#pragma unroll
                for (int ni = 0; ni < 4; ni++)
                    wmma::mma_sync(c[mi][ni], a[mi], b[ni], c[mi][ni]);
        }
        __syncthreads();
    }

#pragma unroll
    for (int mi = 0; mi < 2; mi++)
#pragma unroll
        for (int ni = 0; ni < 4; ni++)
            wmma::store_matrix_sync(&Cs[(wm * 32 + mi * 16) * CS_LD + wn * 64 + ni * 16],
                                    c[mi][ni], CS_LD, wmma::mem_row_major);
    __syncthreads();

    int orow = tx >> 1, ocol = (tx & 1) * 64;
    int pid = sPid[orow];
    if (pid >= 0) {
        float scale = g_pairw[pid];
        float* dst = g_ypair + (size_t)pid * H_DIM + colBase + ocol;
        const float* src = &Cs[orow * CS_LD + ocol];
#pragma unroll
        for (int i = 0; i < 16; i++) {
            float4 v = *(const float4*)(src + i * 4);
            v.x *= scale; v.y *= scale; v.z *= scale; v.w *= scale;
            *(float4*)(dst + i * 4) = v;
        }
    }
}

// ---------------- RoPE ----------------
__global__ void rope_kernel(const float* __restrict__ cosp, const float* __restrict__ sinp)
{
    int idx = blockIdx.x * blockDim.x + threadIdx.x;
    if (idx >= T_TOK * NHEAD * 32) return;
    int d = idx & 31;
    int n = (idx >> 5) & 15;
    int t = idx >> 9;
    int s = t & (S_LEN - 1);
    float c1 = cosp[s * 64 + d],      s1 = sinp[s * 64 + d];
    float c2 = cosp[s * 64 + d + 32], s2 = sinp[s * 64 + d + 32];
    size_t base = (size_t)t * 3072 + n * 64 + d;
    float x1 = g_qkv[base], x2 = g_qkv[base + 32];
    g_qkv[base]      = x1 * c1 - x2 * s1;
    g_qkv[base + 32] = x2 * c2 + x1 * s2;
    base += 1024;
    x1 = g_qkv[base]; x2 = g_qkv[base + 32];
    g_qkv[base]      = x1 * c1 - x2 * s1;
    g_qkv[base + 32] = x2 * c2 + x1 * s2;
}

// ---------------- attention (flash-style) ----------------
__global__ __launch_bounds__(256) void attn_kernel()
{
    extern __shared__ float sm[];
    float* Qs = sm;
    float* Ks = sm + 64 * 65;
    float* Vs = sm + 2 * 64 * 65;

    int qt = blockIdx.x, h = blockIdx.y, b = blockIdx.z;
    int tx = threadIdx.x;
    int row = tx >> 2, sub = tx & 3;
    int tbase = b * S_LEN;

    {
        int lr = tx >> 2, lc = (tx & 3) * 16;
        const float* qp = g_qkv + (size_t)(tbase + qt * 64 + lr) * 3072 + h * 64;
#pragma unroll
        for (int i = 0; i < 4; i++) {
            int c = lc + i * 4;
            float4 v = *(const float4*)(qp + c);
            Qs[lr * 65 + c]     = v.x; Qs[lr * 65 + c + 1] = v.y;
            Qs[lr * 65 + c + 2] = v.z; Qs[lr * 65 + c + 3] = v.w;
        }
    }

    float acc[64];
#pragma unroll
    for (int i = 0; i < 64; i++) acc[i] = 0.f;
    float m = -1e30f, l = 0.f;

    for (int kt = 0; kt < 16; kt++) {
        __syncthreads();
        {
            int lr = tx >> 2, lc = (tx & 3) * 16;
            const float* kp = g_qkv + (size_t)(tbase + kt * 64 + lr) * 3072 + 1024 + h * 64;
            const float* vp = kp + 1024;
#pragma unroll
            for (int i = 0; i < 4; i++) {
                int c = lc + i * 4;
                float4 kv = *(const float4*)(kp + c);
                Ks[lr * 65 + c]     = kv.x; Ks[lr * 65 + c + 1] = kv.y;
                Ks[lr * 65 + c + 2] = kv.z; Ks[lr * 65 + c + 3] = kv.w;
                float4 vv = *(const float4*)(vp + c);
                Vs[lr * 65 + c]     = vv.x; Vs[lr * 65 + c + 1] = vv.y;
                Vs[lr * 65 + c + 2] = vv.z; Vs[lr * 65 + c + 3] = vv.w;
            }
        }
        __syncthreads();

        float sc[16];
#pragma unroll
        for (int jt = 0; jt < 16; jt++) sc[jt] = 0.f;
#pragma unroll
        for (int d = 0; d < 64; d++) {
            float qd = Qs[row * 65 + d];
#pragma unroll
            for (int jt = 0; jt < 16; jt++)
                sc[jt] += qd * Ks[(sub * 16 + jt) * 65 + d];
        }
        float lm = -1e30f;
#pragma unroll
        for (int jt = 0; jt < 16; jt++) { sc[jt] *= 0.125f; lm = fmaxf(lm, sc[jt]); }
        lm = fmaxf(lm, __shfl_xor_sync(0xffffffffu, lm, 1));
        lm = fmaxf(lm, __shfl_xor_sync(0xffffffffu, lm, 2));
        float mn = fmaxf(m, lm);
        float alpha = __expf(m - mn);
        l *= alpha;
#pragma unroll
        for (int d = 0; d < 64; d++) acc[d] *= alpha;
#pragma unroll
        for (int jt = 0; jt < 16; jt++) {
            int j = sub * 16 + jt;
            float p = __expf(sc[jt] - mn);
            l += p;
#pragma unroll
            for (int d = 0; d < 64; d++) acc[d] += p * Vs[j * 65 + d];
        }
        m = mn;
    }

    l += __shfl_xor_sync(0xffffffffu, l, 1);
    l += __shfl_xor_sync(0xffffffffu, l, 2);
#pragma unroll
    for (int d = 0; d < 64; d++) {
        acc[d] += __shfl_xor_sync(0xffffffffu, acc[d], 1);
        acc[d] += __shfl_xor_sync(0xffffffffu, acc[d], 2);
    }
    float inv = 1.f / l;
    int t = tbase + qt * 64 + row;
#pragma unroll
    for (int i = 0; i < 16; i++) {
        int d = sub * 16 + i;
        g_ctx[(size_t)t * H_DIM + h * 64 + d] = acc[d] * inv;
    }
}

// ---------------- block reduce ----------------
__device__ __forceinline__ float blockReduceSum(float v)
{
    __shared__ float red[8];
    int lane = threadIdx.x & 31, warp = threadIdx.x >> 5;
#pragma unroll
    for (int o = 16; o; o >>= 1) v += __shfl_xor_sync(0xffffffffu, v, o);
    if (lane == 0) red[warp] = v;
    __syncthreads();
    if (warp == 0) {
        float t = (lane < 8) ? red[lane] : 0.f;
#pragma unroll
        for (int o = 4; o; o >>= 1) t += __shfl_xor_sync(0xffffffffu, t, o);
        if (lane == 0) red[0] = t;
    }
    __syncthreads();
    return red[0];
}

// ---------------- add + rmsnorm ----------------
__global__ __launch_bounds__(256) void addnorm_kernel(
    const float* __restrict__ a, const float* __restrict__ b, float* __restrict__ out)
{
    int t = blockIdx.x, tx = threadIdx.x;
    const float* ap = a + (size_t)t * H_DIM;
    const float* bp = b + (size_t)t * H_DIM;
    float v[4]; float ss = 0.f;
#pragma unroll
    for (int j = 0; j < 4; j++) {
        int i = tx + j * 256;
        float x = ap[i] + bp[i];
        v[j] = x; ss += x * x;
    }
    float tot = blockReduceSum(ss);
    float scale = rsqrtf(tot * (1.f / H_DIM) + 1e-5f);
    float* op = out + (size_t)t * H_DIM;
#pragma unroll
    for (int j = 0; j < 4; j++) op[tx + j * 256] = v[j] * scale;
}

// ---------------- routing ----------------
__global__ void zerocnt_kernel() { if (threadIdx.x < NEXP) g_cnt[threadIdx.x] = 0; }

__global__ void route_kernel(const float* __restrict__ wg)
{
    int t = blockIdx.x, lane = threadIdx.x;
    float p[8];
#pragma unroll
    for (int e = 0; e < 8; e++) p[e] = 0.f;
    const float* x = g_hs + (size_t)t * H_DIM;
    for (int h = lane; h < H_DIM; h += 32) {
        float xv = x[h];
#pragma unroll
        for (int e = 0; e < 8; e++) p[e] += xv * wg[h * 8 + e];
    }
#pragma unroll
    for (int e = 0; e < 8; e++)
#pragma unroll
        for (int o = 16; o; o >>= 1) p[e] += __shfl_xor_sync(0xffffffffu, p[e], o);

    if (lane == 0) {
        int e0 = 0; float l0 = p[0];
        for (int e = 1; e < 8; e++) if (p[e] > l0) { l0 = p[e]; e0 = e; }
        int e1 = -1; float l1 = -1e30f;
        for (int e = 0; e < 8; e++) if (e != e0 && p[e] > l1) { l1 = p[e]; e1 = e; }
        float w0 = 1.f / (1.f + expf(l1 - l0));
        float w1 = 1.f - w0;
        int pos0 = atomicAdd(&g_cnt[e0], 1);
        g_rows[e0 * T_TOK + pos0] = t * 2;
        g_pairw[t * 2] = w0;
        int pos1 = atomicAdd(&g_cnt[e1], 1);
        g_rows[e1 * T_TOK + pos1] = t * 2 + 1;
        g_pairw[t * 2 + 1] = w1;
    }
}

// ---------------- final rmsnorm ----------------
__global__ __launch_bounds__(256) void final_kernel(float* __restrict__ out)
{
    int t = blockIdx.x, tx = threadIdx.x;
    const float* hs = g_hs + (size_t)t * H_DIM;
    const float* y0 = g_ypair + (size_t)(t * 2) * H_DIM;
    const float* y1 = y0 + H_DIM;
    float v[4]; float ss = 0.f;
#pragma unroll
    for (int j = 0; j < 4; j++) {
        int i = tx + j * 256;
        float x = hs[i] + y0[i] + y1[i];
        v[j] = x; ss += x * x;
    }
    float tot = blockReduceSum(ss);
    float scale = rsqrtf(tot * (1.f / H_DIM) + 1e-5f);
    float* op = out + (size_t)t * H_DIM;
#pragma unroll
    for (int j = 0; j < 4; j++) op[tx + j * 256] = v[j] * scale;
}

// ---------------- launch ----------------
extern "C" void kernel_launch(void* const* d_in, const int* in_sizes, int n_in,
                              void* d_out, int out_size)
{
    const float* hidden = (const float*)d_in[0];
    const float* cosp   = (const float*)d_in[1];
    const float* sinp   = (const float*)d_in[2];
    const float* w_qkv  = (const float*)d_in[3];
    const float* w_o    = (const float*)d_in[4];
    const float* w_gate = (const float*)d_in[5];
    const float* w_gu   = (const float*)d_in[6];
    const float* w_down = (const float*)d_in[7];
    float* out = (float*)d_out;

    float* qkv_ptr; cudaGetSymbolAddress((void**)&qkv_ptr, g_qkv);
    float* ctx_ptr; cudaGetSymbolAddress((void**)&ctx_ptr, g_ctx);
    float* tmp_ptr; cudaGetSymbolAddress((void**)&tmp_ptr, g_tmp);
    float* hs_ptr;  cudaGetSymbolAddress((void**)&hs_ptr,  g_hs);

    const int MOE_SMEM = 128 * CS_LD * 4;   // 67.6 KB (epilogue dominates)
    static bool attrs_set = false;
    if (!attrs_set) {
        cudaFuncSetAttribute(attn_kernel, cudaFuncAttributeMaxDynamicSharedMemorySize, 3 * 64 * 65 * 4);
        cudaFuncSetAttribute(moe_gateup_kernel, cudaFuncAttributeMaxDynamicSharedMemorySize, MOE_SMEM);
        cudaFuncSetAttribute(moe_down_kernel,   cudaFuncAttributeMaxDynamicSharedMemorySize, MOE_SMEM);
        attrs_set = true;
    }

    // 1. QKV projection
    gemm_tf32_kernel<<<dim3(3072 / 128, 2048 / 128), 256>>>(hidden, w_qkv, qkv_ptr, 2048, 3072, 1024);

    // 2. RoPE
    rope_kernel<<<(T_TOK * NHEAD * 32) / 256, 256>>>(cosp, sinp);

    // 3. attention
    attn_kernel<<<dim3(16, 16, 2), 256, 3 * 64 * 65 * 4>>>();

    // 4. O projection
    gemm_tf32_kernel<<<dim3(1024 / 128, 2048 / 128), 256>>>(ctx_ptr, w_o, tmp_ptr, 2048, 1024, 1024);

    // 5. hs = rmsnorm(x + attn_out)
    addnorm_kernel<<<T_TOK, 256>>>(hidden, tmp_ptr, hs_ptr);

    // 6. routing
    zerocnt_kernel<<<1, 32>>>();
    route_kernel<<<T_TOK, 32>>>(w_gate);

    // 7. fused gate_up + silu -> g_act
    moe_gateup_kernel<<<dim3(INTER / 128, 2048 / 128, NEXP), 256, MOE_SMEM>>>(w_gu);

    // 8. down proj (weighted) -> g_ypair
    moe_down_kernel<<<dim3(1024 / 128, 2048 / 128, NEXP), 256, MOE_SMEM>>>(w_down);

    // 9. out = rmsnorm(hs + mixed)
    final_kernel<<<T_TOK, 256>>>(out);
}

// round 6
// speedup vs baseline: 2.0973x; 1.6088x over previous
#include <cuda_runtime.h>
#include <mma.h>
#include <math.h>
#include <cstdint>

using namespace nvcuda;

// ---------------- problem constants ----------------
#define T_TOK 2048
#define S_LEN 1024
#define H_DIM 1024
#define NHEAD 16
#define HD    64
#define NEXP  8
#define INTER 2816
#define GU2   (2*INTER)

// ---------------- device scratch ----------------
__device__ float g_qkv [(size_t)T_TOK * 3 * H_DIM];
__device__ float g_ctx [(size_t)T_TOK * H_DIM];
__device__ float g_tmp [(size_t)T_TOK * H_DIM];
__device__ float g_hs  [(size_t)T_TOK * H_DIM];
__device__ float g_act [(size_t)T_TOK * 2 * INTER];
__device__ float g_ypair[(size_t)T_TOK * 2 * H_DIM];
__device__ float g_scores[(size_t)2 * NHEAD * S_LEN * S_LEN];   // 134 MB
__device__ float g_pairw[T_TOK * 2];
__device__ int   g_cnt [NEXP];
__device__ int   g_rows[NEXP * T_TOK];

// ---------------- cp.async helpers ----------------
__device__ __forceinline__ void cp16(float* s, const float* g, bool pred) {
    unsigned int sa = (unsigned int)__cvta_generic_to_shared(s);
    int sz = pred ? 16 : 0;
    asm volatile("cp.async.cg.shared.global [%0], [%1], 16, %2;\n" :: "r"(sa), "l"(g), "r"(sz));
}
__device__ __forceinline__ void cp_commit() { asm volatile("cp.async.commit_group;\n"); }
__device__ __forceinline__ void cp_wait1()  { asm volatile("cp.async.wait_group 1;\n" ::: "memory"); }
__device__ __forceinline__ void cp_wait0()  { asm volatile("cp.async.wait_group 0;\n" ::: "memory"); }

#define AS_LD 24
#define BS_LD 136
#define CS_LD 132
#define KS_LD 24
#define VS_LD 72

typedef wmma::fragment<wmma::matrix_a, 16, 16, 8, wmma::precision::tf32, wmma::row_major> FragA;
typedef wmma::fragment<wmma::matrix_b, 16, 16, 8, wmma::precision::tf32, wmma::row_major> FragB;
typedef wmma::fragment<wmma::matrix_b, 16, 16, 8, wmma::precision::tf32, wmma::col_major> FragBc;
typedef wmma::fragment<wmma::accumulator, 16, 16, 8, float> FragC;

__device__ __forceinline__ void load_a_frags(FragA a[2], const float* As, int wm, int ks) {
#pragma unroll
    for (int mi = 0; mi < 2; mi++) {
        wmma::load_matrix_sync(a[mi], &As[(wm * 32 + mi * 16) * AS_LD + ks * 8], AS_LD);
#pragma unroll
        for (int i = 0; i < a[mi].num_elements; i++)
            a[mi].x[i] = wmma::__float_to_tf32(a[mi].x[i]);
    }
}
__device__ __forceinline__ void load_b_frags(FragB b[4], const float* Bs, int wn, int ks) {
#pragma unroll
    for (int ni = 0; ni < 4; ni++) {
        wmma::load_matrix_sync(b[ni], &Bs[(ks * 8) * BS_LD + wn * 64 + ni * 16], BS_LD);
#pragma unroll
        for (int i = 0; i < b[ni].num_elements; i++)
            b[ni].x[i] = wmma::__float_to_tf32(b[ni].x[i]);
    }
}

// ================= plain TF32 GEMM, 2-stage cp.async pipeline =================
__global__ __launch_bounds__(256) void gemm_tf32_kernel(
    const float* __restrict__ A, const float* __restrict__ B,
    float* __restrict__ C, int M, int N, int K)
{
    __shared__ float As[2][128 * AS_LD];
    __shared__ float Bs[2][16 * BS_LD];

    int tx = threadIdx.x;
    int rowBase = blockIdx.y * 128;
    int colBase = blockIdx.x * 128;
    int warp = tx >> 5, wm = warp >> 1, wn = warp & 1;

    FragC c[2][4];
#pragma unroll
    for (int mi = 0; mi < 2; mi++)
#pragma unroll
        for (int ni = 0; ni < 4; ni++) wmma::fill_fragment(c[mi][ni], 0.f);

    int arow = tx >> 1, acol = (tx & 1) * 8;
    int brow = tx >> 4, bcol = (tx & 15) * 8;
    const float* aP = A + (size_t)(rowBase + arow) * K + acol;
    const float* bP = B + (size_t)brow * N + colBase + bcol;
    int nt = K >> 4;

    cp16(&As[0][arow * AS_LD + acol],     aP,     true);
    cp16(&As[0][arow * AS_LD + acol + 4], aP + 4, true);
    cp16(&Bs[0][brow * BS_LD + bcol],     bP,     true);
    cp16(&Bs[0][brow * BS_LD + bcol + 4], bP + 4, true);
    cp_commit();

    for (int t = 0; t < nt; t++) {
        int cur = t & 1, nxt = cur ^ 1;
        if (t + 1 < nt) {
            const float* a2 = aP + (t + 1) * 16;
            const float* b2 = bP + (size_t)(t + 1) * 16 * N;
            cp16(&As[nxt][arow * AS_LD + acol],     a2,     true);
            cp16(&As[nxt][arow * AS_LD + acol + 4], a2 + 4, true);
            cp16(&Bs[nxt][brow * BS_LD + bcol],     b2,     true);
            cp16(&Bs[nxt][brow * BS_LD + bcol + 4], b2 + 4, true);
            cp_commit();
            cp_wait1();
        } else cp_wait0();
        __syncthreads();
#pragma unroll
        for (int ks = 0; ks < 2; ks++) {
            FragA a[2]; FragB b[4];
            load_a_frags(a, As[cur], wm, ks);
            load_b_frags(b, Bs[cur], wn, ks);
#pragma unroll
            for (int mi = 0; mi < 2; mi++)
#pragma unroll
                for (int ni = 0; ni < 4; ni++)
                    wmma::mma_sync(c[mi][ni], a[mi], b[ni], c[mi][ni]);
        }
        __syncthreads();
    }
#pragma unroll
    for (int mi = 0; mi < 2; mi++)
#pragma unroll
        for (int ni = 0; ni < 4; ni++)
            wmma::store_matrix_sync(
                &C[(size_t)(rowBase + wm * 32 + mi * 16) * N + colBase + wn * 64 + ni * 16],
                c[mi][ni], N, wmma::mem_row_major);
}

// ================= attention scores: S = 0.125 * Q @ K^T =================
// grid (8 keytiles, 8 qtiles, 32 bh); block 256
__global__ __launch_bounds__(256) void attn_qk_kernel()
{
    __shared__ float As[2][128 * AS_LD];
    __shared__ float Bs[2][128 * KS_LD];

    int z = blockIdx.z;
    int b = z >> 4, h = z & 15;
    int qBase = blockIdx.y * 128, kBase = blockIdx.x * 128;
    int tbase = b * S_LEN;
    int tx = threadIdx.x;
    int warp = tx >> 5, wm = warp >> 1, wn = warp & 1;

    FragC c[2][4];
#pragma unroll
    for (int mi = 0; mi < 2; mi++)
#pragma unroll
        for (int ni = 0; ni < 4; ni++) wmma::fill_fragment(c[mi][ni], 0.f);

    int arow = tx >> 1, acol = (tx & 1) * 8;
    const float* aP = g_qkv + (size_t)(tbase + qBase + arow) * 3072 + h * 64 + acol;
    const float* bP = g_qkv + (size_t)(tbase + kBase + arow) * 3072 + 1024 + h * 64 + acol;
    const int nt = 4;   // K=64

    cp16(&As[0][arow * AS_LD + acol],     aP,     true);
    cp16(&As[0][arow * AS_LD + acol + 4], aP + 4, true);
    cp16(&Bs[0][arow * KS_LD + acol],     bP,     true);
    cp16(&Bs[0][arow * KS_LD + acol + 4], bP + 4, true);
    cp_commit();

    for (int t = 0; t < nt; t++) {
        int cur = t & 1, nxt = cur ^ 1;
        if (t + 1 < nt) {
            const float* a2 = aP + (t + 1) * 16;
            const float* b2 = bP + (t + 1) * 16;
            cp16(&As[nxt][arow * AS_LD + acol],     a2,     true);
            cp16(&As[nxt][arow * AS_LD + acol + 4], a2 + 4, true);
            cp16(&Bs[nxt][arow * KS_LD + acol],     b2,     true);
            cp16(&Bs[nxt][arow * KS_LD + acol + 4], b2 + 4, true);
            cp_commit();
            cp_wait1();
        } else cp_wait0();
        __syncthreads();
#pragma unroll
        for (int ks = 0; ks < 2; ks++) {
            FragA a[2]; FragBc bb[4];
            load_a_frags(a, As[cur], wm, ks);
#pragma unroll
            for (int ni = 0; ni < 4; ni++) {
                wmma::load_matrix_sync(bb[ni], &Bs[cur][(wn * 64 + ni * 16) * KS_LD + ks * 8], KS_LD);
#pragma unroll
                for (int i = 0; i < bb[ni].num_elements; i++)
                    bb[ni].x[i] = wmma::__float_to_tf32(bb[ni].x[i]);
            }
#pragma unroll
            for (int mi = 0; mi < 2; mi++)
#pragma unroll
                for (int ni = 0; ni < 4; ni++)
                    wmma::mma_sync(c[mi][ni], a[mi], bb[ni], c[mi][ni]);
        }
        __syncthreads();
    }

    float* Sbase = g_scores + (size_t)z * S_LEN * S_LEN;
#pragma unroll
    for (int mi = 0; mi < 2; mi++)
#pragma unroll
        for (int ni = 0; ni < 4; ni++) {
#pragma unroll
            for (int i = 0; i < c[mi][ni].num_elements; i++) c[mi][ni].x[i] *= 0.125f;
            wmma::store_matrix_sync(
                &Sbase[(size_t)(qBase + wm * 32 + mi * 16) * S_LEN + kBase + wn * 64 + ni * 16],
                c[mi][ni], S_LEN, wmma::mem_row_major);
        }
}

// ================= row softmax over g_scores (one warp per 1024-row) =================
__global__ __launch_bounds__(256) void softmax_kernel()
{
    int row = blockIdx.x * 8 + (threadIdx.x >> 5);
    int lane = threadIdx.x & 31;
    float* p = g_scores + (size_t)row * S_LEN;

    float4 v[8];
    float mx = -1e30f;
#pragma unroll
    for (int i = 0; i < 8; i++) {
        v[i] = *(const float4*)(p + (i * 32 + lane) * 4);
        mx = fmaxf(mx, fmaxf(fmaxf(v[i].x, v[i].y), fmaxf(v[i].z, v[i].w)));
    }
#pragma unroll
    for (int o = 16; o; o >>= 1) mx = fmaxf(mx, __shfl_xor_sync(0xffffffffu, mx, o));
    float sum = 0.f;
#pragma unroll
    for (int i = 0; i < 8; i++) {
        v[i].x = __expf(v[i].x - mx); v[i].y = __expf(v[i].y - mx);
        v[i].z = __expf(v[i].z - mx); v[i].w = __expf(v[i].w - mx);
        sum += v[i].x + v[i].y + v[i].z + v[i].w;
    }
#pragma unroll
    for (int o = 16; o; o >>= 1) sum += __shfl_xor_sync(0xffffffffu, sum, o);
    float inv = 1.f / sum;
#pragma unroll
    for (int i = 0; i < 8; i++) {
        v[i].x *= inv; v[i].y *= inv; v[i].z *= inv; v[i].w *= inv;
        *(float4*)(p + (i * 32 + lane) * 4) = v[i];
    }
}

// ================= attention PV: ctx = P @ V  (128m x 64n, K=1024) =================
// grid (8 mtiles, 32 bh); block 256, 8 warps 4m x 2n, warp 32x32
__global__ __launch_bounds__(256) void attn_pv_kernel()
{
    __shared__ float As[2][128 * AS_LD];
    __shared__ float Bs[2][16 * VS_LD];

    int z = blockIdx.y;
    int b = z >> 4, h = z & 15;
    int mBase = blockIdx.x * 128;
    int tbase = b * S_LEN;
    int tx = threadIdx.x;
    int warp = tx >> 5, wm = warp >> 1, wn = warp & 1;

    FragC c[2][2];
#pragma unroll
    for (int mi = 0; mi < 2; mi++)
#pragma unroll
        for (int ni = 0; ni < 2; ni++) wmma::fill_fragment(c[mi][ni], 0.f);

    int arow = tx >> 1, acol = (tx & 1) * 8;
    int brow = tx >> 4, bcol = (tx & 15) * 4;
    const float* aP = g_scores + (size_t)z * S_LEN * S_LEN + (size_t)(mBase + arow) * S_LEN + acol;
    const float* bP = g_qkv + (size_t)(tbase + brow) * 3072 + 2048 + h * 64 + bcol;
    const int nt = S_LEN >> 4;   // 64

    cp16(&As[0][arow * AS_LD + acol],     aP,     true);
    cp16(&As[0][arow * AS_LD + acol + 4], aP + 4, true);
    cp16(&Bs[0][brow * VS_LD + bcol],     bP,     true);
    cp_commit();

    for (int t = 0; t < nt; t++) {
        int cur = t & 1, nxt = cur ^ 1;
        if (t + 1 < nt) {
            const float* a2 = aP + (t + 1) * 16;
            const float* b2 = bP + (size_t)(t + 1) * 16 * 3072;
            cp16(&As[nxt][arow * AS_LD + acol],     a2,     true);
            cp16(&As[nxt][arow * AS_LD + acol + 4], a2 + 4, true);
            cp16(&Bs[nxt][brow * VS_LD + bcol],     b2,     true);
            cp_commit();
            cp_wait1();
        } else cp_wait0();
        __syncthreads();
#pragma unroll
        for (int ks = 0; ks < 2; ks++) {
            FragA a[2]; FragB bb[2];
            load_a_frags(a, As[cur], wm, ks);
#pragma unroll
            for (int ni = 0; ni < 2; ni++) {
                wmma::load_matrix_sync(bb[ni], &Bs[cur][(ks * 8) * VS_LD + wn * 32 + ni * 16], VS_LD);
#pragma unroll
                for (int i = 0; i < bb[ni].num_elements; i++)
                    bb[ni].x[i] = wmma::__float_to_tf32(bb[ni].x[i]);
            }
#pragma unroll
            for (int mi = 0; mi < 2; mi++)
#pragma unroll
                for (int ni = 0; ni < 2; ni++)
                    wmma::mma_sync(c[mi][ni], a[mi], bb[ni], c[mi][ni]);
        }
        __syncthreads();
    }

#pragma unroll
    for (int mi = 0; mi < 2; mi++)
#pragma unroll
        for (int ni = 0; ni < 2; ni++)
            wmma::store_matrix_sync(
                &g_ctx[(size_t)(tbase + mBase + wm * 32 + mi * 16) * H_DIM + h * 64 + wn * 32 + ni * 16],
                c[mi][ni], H_DIM, wmma::mem_row_major);
}

// ================= MoE gate_up fused silu =================
__global__ __launch_bounds__(256) void moe_gateup_kernel(const float* __restrict__ Wgu)
{
    extern __shared__ float sm[];
    float* As = sm;
    float* Bg = sm + 2 * 128 * AS_LD;
    float* Bu = Bg + 2 * 16 * BS_LD;
    float* Cs = sm;
    __shared__ int sPid[128];

    int e = blockIdx.z;
    int count = g_cnt[e];
    int mBase = blockIdx.y * 128;
    if (mBase >= count) return;
    int nBase = blockIdx.x * 128;

    int tx = threadIdx.x;
    if (tx < 128) {
        int r = mBase + tx;
        sPid[tx] = (r < count) ? g_rows[e * T_TOK + r] : -1;
    }
    __syncthreads();

    const float* B = Wgu + (size_t)e * H_DIM * GU2;
    int warp = tx >> 5, wm = warp >> 1, wn = warp & 1;

    FragC cg[2][4], cu[2][4];
#pragma unroll
    for (int mi = 0; mi < 2; mi++)
#pragma unroll
        for (int ni = 0; ni < 4; ni++) { wmma::fill_fragment(cg[mi][ni], 0.f); wmma::fill_fragment(cu[mi][ni], 0.f); }

    int arow = tx >> 1, acol = (tx & 1) * 8;
    int brow = tx >> 4, bcol = (tx & 15) * 8;
    int pidA = sPid[arow];
    bool valid = (pidA >= 0);
    const float* aP = g_hs + (valid ? (size_t)(pidA >> 1) * H_DIM : 0) + acol;
    const float* bgP = B + (size_t)brow * GU2 + nBase + bcol;
    const float* buP = bgP + INTER;
    const int nt = H_DIM >> 4;

    cp16(&As[0 * 128 * AS_LD + arow * AS_LD + acol],     aP,      valid);
    cp16(&As[0 * 128 * AS_LD + arow * AS_LD + acol + 4], aP + 4,  valid);
    cp16(&Bg[0 * 16 * BS_LD + brow * BS_LD + bcol],      bgP,     true);
    cp16(&Bg[0 * 16 * BS_LD + brow * BS_LD + bcol + 4],  bgP + 4, true);
    cp16(&Bu[0 * 16 * BS_LD + brow * BS_LD + bcol],      buP,     true);
    cp16(&Bu[0 * 16 * BS_LD + brow * BS_LD + bcol + 4],  buP + 4, true);
    cp_commit();

    for (int t = 0; t < nt; t++) {
        int cur = t & 1, nxt = cur ^ 1;
        if (t + 1 < nt) {
            const float* a2 = aP + (t + 1) * 16;
            const float* bg2 = bgP + (size_t)(t + 1) * 16 * GU2;
            const float* bu2 = buP + (size_t)(t + 1) * 16 * GU2;
            cp16(&As[nxt * 128 * AS_LD + arow * AS_LD + acol],     a2,      valid);
            cp16(&As[nxt * 128 * AS_LD + arow * AS_LD + acol + 4], a2 + 4,  valid);
            cp16(&Bg[nxt * 16 * BS_LD + brow * BS_LD + bcol],      bg2,     true);
            cp16(&Bg[nxt * 16 * BS_LD + brow * BS_LD + bcol + 4],  bg2 + 4, true);
            cp16(&Bu[nxt * 16 * BS_LD + brow * BS_LD + bcol],      bu2,     true);
            cp16(&Bu[nxt * 16 * BS_LD + brow * BS_LD + bcol + 4],  bu2 + 4, true);
            cp_commit();
            cp_wait1();
        } else cp_wait0();
        __syncthreads();
#pragma unroll
        for (int ks = 0; ks < 2; ks++) {
            FragA a[2]; FragB bg[4], bu[4];
            load_a_frags(a, &As[cur * 128 * AS_LD], wm, ks);
            load_b_frags(bg, &Bg[cur * 16 * BS_LD], wn, ks);
            load_b_frags(bu, &Bu[cur * 16 * BS_LD], wn, ks);
#pragma unroll
            for (int mi = 0; mi < 2; mi++)
#pragma unroll
                for (int ni = 0; ni < 4; ni++) {
                    wmma::mma_sync(cg[mi][ni], a[mi], bg[ni], cg[mi][ni]);
                    wmma::mma_sync(cu[mi][ni], a[mi], bu[ni], cu[mi][ni]);
                }
        }
        __syncthreads();
    }

#pragma unroll
    for (int mi = 0; mi < 2; mi++)
#pragma unroll
        for (int ni = 0; ni < 4; ni++) {
#pragma unroll
            for (int i = 0; i < cg[mi][ni].num_elements; i++) {
                float g = cg[mi][ni].x[i];
                cg[mi][ni].x[i] = g / (1.f + __expf(-g)) * cu[mi][ni].x[i];
            }
            wmma::store_matrix_sync(&Cs[(wm * 32 + mi * 16) * CS_LD + wn * 64 + ni * 16],
                                    cg[mi][ni], CS_LD, wmma::mem_row_major);
        }
    __syncthreads();

    int orow = tx >> 1, ocol = (tx & 1) * 64;
    int pid = sPid[orow];
    if (pid >= 0) {
        float* dst = g_act + (size_t)pid * INTER + nBase + ocol;
        const float* src = &Cs[orow * CS_LD + ocol];
#pragma unroll
        for (int i = 0; i < 16; i++)
            *(float4*)(dst + i * 4) = *(const float4*)(src + i * 4);
    }
}

// ================= MoE down =================
__global__ __launch_bounds__(256) void moe_down_kernel(const float* __restrict__ Wd)
{
    extern __shared__ float sm[];
    float* As = sm;
    float* Bs = sm + 2 * 128 * AS_LD;
    float* Cs = sm;
    __shared__ int sPid[128];

    int e = blockIdx.z;
    int count = g_cnt[e];
    int mBase = blockIdx.y * 128;
    if (mBase >= count) return;
    int colBase = blockIdx.x * 128;

    int tx = threadIdx.x;
    if (tx < 128) {
        int r = mBase + tx;
        sPid[tx] = (r < count) ? g_rows[e * T_TOK + r] : -1;
    }
    __syncthreads();

    const float* B = Wd + (size_t)e * INTER * H_DIM;
    int warp = tx >> 5, wm = warp >> 1, wn = warp & 1;

    FragC c[2][4];
#pragma unroll
    for (int mi = 0; mi < 2; mi++)
#pragma unroll
        for (int ni = 0; ni < 4; ni++) wmma::fill_fragment(c[mi][ni], 0.f);

    int arow = tx >> 1, acol = (tx & 1) * 8;
    int brow = tx >> 4, bcol = (tx & 15) * 8;
    int pidA = sPid[arow];
    bool valid = (pidA >= 0);
    const float* aP = g_act + (valid ? (size_t)pidA * INTER : 0) + acol;
    const float* bP = B + (size_t)brow * H_DIM + colBase + bcol;
    const int nt = INTER >> 4;

    cp16(&As[0 * 128 * AS_LD + arow * AS_LD + acol],     aP,     valid);
    cp16(&As[0 * 128 * AS_LD + arow * AS_LD + acol + 4], aP + 4, valid);
    cp16(&Bs[0 * 16 * BS_LD + brow * BS_LD + bcol],      bP,     true);
    cp16(&Bs[0 * 16 * BS_LD + brow * BS_LD + bcol + 4],  bP + 4, true);
    cp_commit();

    for (int t = 0; t < nt; t++) {
        int cur = t & 1, nxt = cur ^ 1;
        if (t + 1 < nt) {
            const float* a2 = aP + (t + 1) * 16;
            const float* b2 = bP + (size_t)(t + 1) * 16 * H_DIM;
            cp16(&As[nxt * 128 * AS_LD + arow * AS_LD + acol],     a2,     valid);
            cp16(&As[nxt * 128 * AS_LD + arow * AS_LD + acol + 4], a2 + 4, valid);
            cp16(&Bs[nxt * 16 * BS_LD + brow * BS_LD + bcol],      b2,     true);
            cp16(&Bs[nxt * 16 * BS_LD + brow * BS_LD + bcol + 4],  b2 + 4, true);
            cp_commit();
            cp_wait1();
        } else cp_wait0();
        __syncthreads();
#pragma unroll
        for (int ks = 0; ks < 2; ks++) {
            FragA a[2]; FragB b[4];
            load_a_frags(a, &As[cur * 128 * AS_LD], wm, ks);
            load_b_frags(b, &Bs[cur * 16 * BS_LD], wn, ks);
#pragma unroll
            for (int mi = 0; mi < 2; mi++)
#pragma unroll
                for (int ni = 0; ni < 4; ni++)
                    wmma::mma_sync(c[mi][ni], a[mi], b[ni], c[mi][ni]);
        }
        __syncthreads();
    }

#pragma unroll
    for (int mi = 0; mi < 2; mi++)
#pragma unroll
        for (int ni = 0; ni < 4; ni++)
            wmma::store_matrix_sync(&Cs[(wm * 32 + mi * 16) * CS_LD + wn * 64 + ni * 16],
                                    c[mi][ni], CS_LD, wmma::mem_row_major);
    __syncthreads();

    int orow = tx >> 1, ocol = (tx & 1) * 64;
    int pid = sPid[orow];
    if (pid >= 0) {
        float scale = g_pairw[pid];
        float* dst = g_ypair + (size_t)pid * H_DIM + colBase + ocol;
        const float* src = &Cs[orow * CS_LD + ocol];
#pragma unroll
        for (int i = 0; i < 16; i++) {
            float4 v = *(const float4*)(src + i * 4);
            v.x *= scale; v.y *= scale; v.z *= scale; v.w *= scale;
            *(float4*)(dst + i * 4) = v;
        }
    }
}

// ---------------- RoPE ----------------
__global__ void rope_kernel(const float* __restrict__ cosp, const float* __restrict__ sinp)
{
    int idx = blockIdx.x * blockDim.x + threadIdx.x;
    if (idx >= T_TOK * NHEAD * 32) return;
    int d = idx & 31;
    int n = (idx >> 5) & 15;
    int t = idx >> 9;
    int s = t & (S_LEN - 1);
    float c1 = cosp[s * 64 + d],      s1 = sinp[s * 64 + d];
    float c2 = cosp[s * 64 + d + 32], s2 = sinp[s * 64 + d + 32];
    size_t base = (size_t)t * 3072 + n * 64 + d;
    float x1 = g_qkv[base], x2 = g_qkv[base + 32];
    g_qkv[base]      = x1 * c1 - x2 * s1;
    g_qkv[base + 32] = x2 * c2 + x1 * s2;
    base += 1024;
    x1 = g_qkv[base]; x2 = g_qkv[base + 32];
    g_qkv[base]      = x1 * c1 - x2 * s1;
    g_qkv[base + 32] = x2 * c2 + x1 * s2;
}

// ---------------- block reduce ----------------
__device__ __forceinline__ float blockReduceSum(float v)
{
    __shared__ float red[8];
    int lane = threadIdx.x & 31, warp = threadIdx.x >> 5;
#pragma unroll
    for (int o = 16; o; o >>= 1) v += __shfl_xor_sync(0xffffffffu, v, o);
    if (lane == 0) red[warp] = v;
    __syncthreads();
    if (warp == 0) {
        float t = (lane < 8) ? red[lane] : 0.f;
#pragma unroll
        for (int o = 4; o; o >>= 1) t += __shfl_xor_sync(0xffffffffu, t, o);
        if (lane == 0) red[0] = t;
    }
    __syncthreads();
    return red[0];
}

// ---------------- add + rmsnorm ----------------
__global__ __launch_bounds__(256) void addnorm_kernel(
    const float* __restrict__ a, const float* __restrict__ b, float* __restrict__ out)
{
    int t = blockIdx.x, tx = threadIdx.x;
    const float* ap = a + (size_t)t * H_DIM;
    const float* bp = b + (size_t)t * H_DIM;
    float v[4]; float ss = 0.f;
#pragma unroll
    for (int j = 0; j < 4; j++) {
        int i = tx + j * 256;
        float x = ap[i] + bp[i];
        v[j] = x; ss += x * x;
    }
    float tot = blockReduceSum(ss);
    float scale = rsqrtf(tot * (1.f / H_DIM) + 1e-5f);
    float* op = out + (size_t)t * H_DIM;
#pragma unroll
    for (int j = 0; j < 4; j++) op[tx + j * 256] = v[j] * scale;
}

// ---------------- routing ----------------
__global__ void zerocnt_kernel() { if (threadIdx.x < NEXP) g_cnt[threadIdx.x] = 0; }

__global__ void route_kernel(const float* __restrict__ wg)
{
    int t = blockIdx.x, lane = threadIdx.x;
    float p[8];
#pragma unroll
    for (int e = 0; e < 8; e++) p[e] = 0.f;
    const float* x = g_hs + (size_t)t * H_DIM;
    for (int h = lane; h < H_DIM; h += 32) {
        float xv = x[h];
#pragma unroll
        for (int e = 0; e < 8; e++) p[e] += xv * wg[h * 8 + e];
    }
#pragma unroll
    for (int e = 0; e < 8; e++)
#pragma unroll
        for (int o = 16; o; o >>= 1) p[e] += __shfl_xor_sync(0xffffffffu, p[e], o);

    if (lane == 0) {
        int e0 = 0; float l0 = p[0];
        for (int e = 1; e < 8; e++) if (p[e] > l0) { l0 = p[e]; e0 = e; }
        int e1 = -1; float l1 = -1e30f;
        for (int e = 0; e < 8; e++) if (e != e0 && p[e] > l1) { l1 = p[e]; e1 = e; }
        float w0 = 1.f / (1.f + expf(l1 - l0));
        float w1 = 1.f - w0;
        int pos0 = atomicAdd(&g_cnt[e0], 1);
        g_rows[e0 * T_TOK + pos0] = t * 2;
        g_pairw[t * 2] = w0;
        int pos1 = atomicAdd(&g_cnt[e1], 1);
        g_rows[e1 * T_TOK + pos1] = t * 2 + 1;
        g_pairw[t * 2 + 1] = w1;
    }
}

// ---------------- final rmsnorm ----------------
__global__ __launch_bounds__(256) void final_kernel(float* __restrict__ out)
{
    int t = blockIdx.x, tx = threadIdx.x;
    const float* hs = g_hs + (size_t)t * H_DIM;
    const float* y0 = g_ypair + (size_t)(t * 2) * H_DIM;
    const float* y1 = y0 + H_DIM;
    float v[4]; float ss = 0.f;
#pragma unroll
    for (int j = 0; j < 4; j++) {
        int i = tx + j * 256;
        float x = hs[i] + y0[i] + y1[i];
        v[j] = x; ss += x * x;
    }
    float tot = blockReduceSum(ss);
    float scale = rsqrtf(tot * (1.f / H_DIM) + 1e-5f);
    float* op = out + (size_t)t * H_DIM;
#pragma unroll
    for (int j = 0; j < 4; j++) op[tx + j * 256] = v[j] * scale;
}

// ---------------- launch ----------------
extern "C" void kernel_launch(void* const* d_in, const int* in_sizes, int n_in,
                              void* d_out, int out_size)
{
    const float* hidden = (const float*)d_in[0];
    const float* cosp   = (const float*)d_in[1];
    const float* sinp   = (const float*)d_in[2];
    const float* w_qkv  = (const float*)d_in[3];
    const float* w_o    = (const float*)d_in[4];
    const float* w_gate = (const float*)d_in[5];
    const float* w_gu   = (const float*)d_in[6];
    const float* w_down = (const float*)d_in[7];
    float* out = (float*)d_out;

    float* qkv_ptr; cudaGetSymbolAddress((void**)&qkv_ptr, g_qkv);
    float* ctx_ptr; cudaGetSymbolAddress((void**)&ctx_ptr, g_ctx);
    float* tmp_ptr; cudaGetSymbolAddress((void**)&tmp_ptr, g_tmp);
    float* hs_ptr;  cudaGetSymbolAddress((void**)&hs_ptr,  g_hs);

    const int MOE_SMEM = 128 * CS_LD * 4;
    static bool attrs_set = false;
    if (!attrs_set) {
        cudaFuncSetAttribute(moe_gateup_kernel, cudaFuncAttributeMaxDynamicSharedMemorySize, MOE_SMEM);
        cudaFuncSetAttribute(moe_down_kernel,   cudaFuncAttributeMaxDynamicSharedMemorySize, MOE_SMEM);
        attrs_set = true;
    }

    // 1. QKV projection
    gemm_tf32_kernel<<<dim3(3072 / 128, 2048 / 128), 256>>>(hidden, w_qkv, qkv_ptr, 2048, 3072, 1024);

    // 2. RoPE
    rope_kernel<<<(T_TOK * NHEAD * 32) / 256, 256>>>(cosp, sinp);

    // 3. attention: QK^T -> softmax -> PV (all tensor-core / bandwidth)
    attn_qk_kernel<<<dim3(8, 8, 32), 256>>>();
    softmax_kernel<<<(2 * NHEAD * S_LEN) / 8, 256>>>();
    attn_pv_kernel<<<dim3(8, 32), 256>>>();

    // 4. O projection
    gemm_tf32_kernel<<<dim3(1024 / 128, 2048 / 128), 256>>>(ctx_ptr, w_o, tmp_ptr, 2048, 1024, 1024);

    // 5. hs = rmsnorm(x + attn_out)
    addnorm_kernel<<<T_TOK, 256>>>(hidden, tmp_ptr, hs_ptr);

    // 6. routing
    zerocnt_kernel<<<1, 32>>>();
    route_kernel<<<T_TOK, 32>>>(w_gate);

    // 7. fused gate_up + silu -> g_act
    moe_gateup_kernel<<<dim3(INTER / 128, 2048 / 128, NEXP), 256, MOE_SMEM>>>(w_gu);

    // 8. down proj (weighted) -> g_ypair
    moe_down_kernel<<<dim3(1024 / 128, 2048 / 128, NEXP), 256, MOE_SMEM>>>(w_down);

    // 9. out = rmsnorm(hs + mixed)
    final_kernel<<<T_TOK, 256>>>(out);
}

// round 7
// speedup vs baseline: 2.1179x; 1.0098x over previous
#include <cuda_runtime.h>
#include <mma.h>
#include <math.h>
#include <cstdint>

using namespace nvcuda;

// ---------------- problem constants ----------------
#define T_TOK 2048
#define S_LEN 1024
#define H_DIM 1024
#define NHEAD 16
#define HD    64
#define NEXP  8
#define INTER 2816
#define GU2   (2*INTER)

// ---------------- device scratch ----------------
__device__ float g_qkv [(size_t)T_TOK * 3 * H_DIM];
__device__ float g_ctx [(size_t)T_TOK * H_DIM];
__device__ float g_tmp [(size_t)T_TOK * H_DIM];
__device__ float g_hs  [(size_t)T_TOK * H_DIM];
__device__ float g_act [(size_t)T_TOK * 2 * INTER];
__device__ float g_ypair[(size_t)T_TOK * 2 * H_DIM];
__device__ float g_scores[(size_t)2 * NHEAD * S_LEN * S_LEN];
__device__ float g_pairw[T_TOK * 2];
__device__ int   g_cnt [NEXP];
__device__ int   g_rows[NEXP * T_TOK];

// ---------------- cp.async helpers ----------------
__device__ __forceinline__ void cp16(float* s, const float* g, bool pred) {
    unsigned int sa = (unsigned int)__cvta_generic_to_shared(s);
    int sz = pred ? 16 : 0;
    asm volatile("cp.async.cg.shared.global [%0], [%1], 16, %2;\n" :: "r"(sa), "l"(g), "r"(sz));
}
__device__ __forceinline__ void cp_commit() { asm volatile("cp.async.commit_group;\n"); }
__device__ __forceinline__ void cp_wait1()  { asm volatile("cp.async.wait_group 1;\n" ::: "memory"); }
__device__ __forceinline__ void cp_wait0()  { asm volatile("cp.async.wait_group 0;\n" ::: "memory"); }

#define AS_LD 24
#define BS_LD 136
#define CS_LD 132
#define KS_LD 24
#define VS_LD 72
#define GS_LD 72      // gate/up B stage: 16 x 64 (+pad)
#define GC_LD 68      // gate_up epilogue stage: 128 x 64 (+pad)

typedef wmma::fragment<wmma::matrix_a, 16, 16, 8, wmma::precision::tf32, wmma::row_major> FragA;
typedef wmma::fragment<wmma::matrix_b, 16, 16, 8, wmma::precision::tf32, wmma::row_major> FragB;
typedef wmma::fragment<wmma::matrix_b, 16, 16, 8, wmma::precision::tf32, wmma::col_major> FragBc;
typedef wmma::fragment<wmma::accumulator, 16, 16, 8, float> FragC;

__device__ __forceinline__ void load_a_frags(FragA a[2], const float* As, int wm, int ks) {
#pragma unroll
    for (int mi = 0; mi < 2; mi++) {
        wmma::load_matrix_sync(a[mi], &As[(wm * 32 + mi * 16) * AS_LD + ks * 8], AS_LD);
#pragma unroll
        for (int i = 0; i < a[mi].num_elements; i++)
            a[mi].x[i] = wmma::__float_to_tf32(a[mi].x[i]);
    }
}
__device__ __forceinline__ void load_b_frags(FragB b[4], const float* Bs, int wn, int ks) {
#pragma unroll
    for (int ni = 0; ni < 4; ni++) {
        wmma::load_matrix_sync(b[ni], &Bs[(ks * 8) * BS_LD + wn * 64 + ni * 16], BS_LD);
#pragma unroll
        for (int i = 0; i < b[ni].num_elements; i++)
            b[ni].x[i] = wmma::__float_to_tf32(b[ni].x[i]);
    }
}

// ================= plain TF32 GEMM, 2-stage cp.async pipeline =================
__global__ __launch_bounds__(256) void gemm_tf32_kernel(
    const float* __restrict__ A, const float* __restrict__ B,
    float* __restrict__ C, int M, int N, int K)
{
    __shared__ float As[2][128 * AS_LD];
    __shared__ float Bs[2][16 * BS_LD];

    int tx = threadIdx.x;
    int rowBase = blockIdx.y * 128;
    int colBase = blockIdx.x * 128;
    int warp = tx >> 5, wm = warp >> 1, wn = warp & 1;

    FragC c[2][4];
#pragma unroll
    for (int mi = 0; mi < 2; mi++)
#pragma unroll
        for (int ni = 0; ni < 4; ni++) wmma::fill_fragment(c[mi][ni], 0.f);

    int arow = tx >> 1, acol = (tx & 1) * 8;
    int brow = tx >> 4, bcol = (tx & 15) * 8;
    const float* aP = A + (size_t)(rowBase + arow) * K + acol;
    const float* bP = B + (size_t)brow * N + colBase + bcol;
    int nt = K >> 4;

    cp16(&As[0][arow * AS_LD + acol],     aP,     true);
    cp16(&As[0][arow * AS_LD + acol + 4], aP + 4, true);
    cp16(&Bs[0][brow * BS_LD + bcol],     bP,     true);
    cp16(&Bs[0][brow * BS_LD + bcol + 4], bP + 4, true);
    cp_commit();

    for (int t = 0; t < nt; t++) {
        int cur = t & 1, nxt = cur ^ 1;
        if (t + 1 < nt) {
            const float* a2 = aP + (t + 1) * 16;
            const float* b2 = bP + (size_t)(t + 1) * 16 * N;
            cp16(&As[nxt][arow * AS_LD + acol],     a2,     true);
            cp16(&As[nxt][arow * AS_LD + acol + 4], a2 + 4, true);
            cp16(&Bs[nxt][brow * BS_LD + bcol],     b2,     true);
            cp16(&Bs[nxt][brow * BS_LD + bcol + 4], b2 + 4, true);
            cp_commit();
            cp_wait1();
        } else cp_wait0();
        __syncthreads();
#pragma unroll
        for (int ks = 0; ks < 2; ks++) {
            FragA a[2]; FragB b[4];
            load_a_frags(a, As[cur], wm, ks);
            load_b_frags(b, Bs[cur], wn, ks);
#pragma unroll
            for (int mi = 0; mi < 2; mi++)
#pragma unroll
                for (int ni = 0; ni < 4; ni++)
                    wmma::mma_sync(c[mi][ni], a[mi], b[ni], c[mi][ni]);
        }
        __syncthreads();
    }
#pragma unroll
    for (int mi = 0; mi < 2; mi++)
#pragma unroll
        for (int ni = 0; ni < 4; ni++)
            wmma::store_matrix_sync(
                &C[(size_t)(rowBase + wm * 32 + mi * 16) * N + colBase + wn * 64 + ni * 16],
                c[mi][ni], N, wmma::mem_row_major);
}

// ================= attention scores: S = 0.125 * Q @ K^T =================
__global__ __launch_bounds__(256) void attn_qk_kernel()
{
    __shared__ float As[2][128 * AS_LD];
    __shared__ float Bs[2][128 * KS_LD];

    int z = blockIdx.z;
    int b = z >> 4, h = z & 15;
    int qBase = blockIdx.y * 128, kBase = blockIdx.x * 128;
    int tbase = b * S_LEN;
    int tx = threadIdx.x;
    int warp = tx >> 5, wm = warp >> 1, wn = warp & 1;

    FragC c[2][4];
#pragma unroll
    for (int mi = 0; mi < 2; mi++)
#pragma unroll
        for (int ni = 0; ni < 4; ni++) wmma::fill_fragment(c[mi][ni], 0.f);

    int arow = tx >> 1, acol = (tx & 1) * 8;
    const float* aP = g_qkv + (size_t)(tbase + qBase + arow) * 3072 + h * 64 + acol;
    const float* bP = g_qkv + (size_t)(tbase + kBase + arow) * 3072 + 1024 + h * 64 + acol;
    const int nt = 4;

    cp16(&As[0][arow * AS_LD + acol],     aP,     true);
    cp16(&As[0][arow * AS_LD + acol + 4], aP + 4, true);
    cp16(&Bs[0][arow * KS_LD + acol],     bP,     true);
    cp16(&Bs[0][arow * KS_LD + acol + 4], bP + 4, true);
    cp_commit();

    for (int t = 0; t < nt; t++) {
        int cur = t & 1, nxt = cur ^ 1;
        if (t + 1 < nt) {
            const float* a2 = aP + (t + 1) * 16;
            const float* b2 = bP + (t + 1) * 16;
            cp16(&As[nxt][arow * AS_LD + acol],     a2,     true);
            cp16(&As[nxt][arow * AS_LD + acol + 4], a2 + 4, true);
            cp16(&Bs[nxt][arow * KS_LD + acol],     b2,     true);
            cp16(&Bs[nxt][arow * KS_LD + acol + 4], b2 + 4, true);
            cp_commit();
            cp_wait1();
        } else cp_wait0();
        __syncthreads();
#pragma unroll
        for (int ks = 0; ks < 2; ks++) {
            FragA a[2]; FragBc bb[4];
            load_a_frags(a, As[cur], wm, ks);
#pragma unroll
            for (int ni = 0; ni < 4; ni++) {
                wmma::load_matrix_sync(bb[ni], &Bs[cur][(wn * 64 + ni * 16) * KS_LD + ks * 8], KS_LD);
#pragma unroll
                for (int i = 0; i < bb[ni].num_elements; i++)
                    bb[ni].x[i] = wmma::__float_to_tf32(bb[ni].x[i]);
            }
#pragma unroll
            for (int mi = 0; mi < 2; mi++)
#pragma unroll
                for (int ni = 0; ni < 4; ni++)
                    wmma::mma_sync(c[mi][ni], a[mi], bb[ni], c[mi][ni]);
        }
        __syncthreads();
    }

    float* Sbase = g_scores + (size_t)z * S_LEN * S_LEN;
#pragma unroll
    for (int mi = 0; mi < 2; mi++)
#pragma unroll
        for (int ni = 0; ni < 4; ni++) {
#pragma unroll
            for (int i = 0; i < c[mi][ni].num_elements; i++) c[mi][ni].x[i] *= 0.125f;
            wmma::store_matrix_sync(
                &Sbase[(size_t)(qBase + wm * 32 + mi * 16) * S_LEN + kBase + wn * 64 + ni * 16],
                c[mi][ni], S_LEN, wmma::mem_row_major);
        }
}

// ================= row softmax =================
__global__ __launch_bounds__(256) void softmax_kernel()
{
    int row = blockIdx.x * 8 + (threadIdx.x >> 5);
    int lane = threadIdx.x & 31;
    float* p = g_scores + (size_t)row * S_LEN;

    float4 v[8];
    float mx = -1e30f;
#pragma unroll
    for (int i = 0; i < 8; i++) {
        v[i] = *(const float4*)(p + (i * 32 + lane) * 4);
        mx = fmaxf(mx, fmaxf(fmaxf(v[i].x, v[i].y), fmaxf(v[i].z, v[i].w)));
    }
#pragma unroll
    for (int o = 16; o; o >>= 1) mx = fmaxf(mx, __shfl_xor_sync(0xffffffffu, mx, o));
    float sum = 0.f;
#pragma unroll
    for (int i = 0; i < 8; i++) {
        v[i].x = __expf(v[i].x - mx); v[i].y = __expf(v[i].y - mx);
        v[i].z = __expf(v[i].z - mx); v[i].w = __expf(v[i].w - mx);
        sum += v[i].x + v[i].y + v[i].z + v[i].w;
    }
#pragma unroll
    for (int o = 16; o; o >>= 1) sum += __shfl_xor_sync(0xffffffffu, sum, o);
    float inv = 1.f / sum;
#pragma unroll
    for (int i = 0; i < 8; i++) {
        v[i].x *= inv; v[i].y *= inv; v[i].z *= inv; v[i].w *= inv;
        *(float4*)(p + (i * 32 + lane) * 4) = v[i];
    }
}

// ================= attention PV =================
__global__ __launch_bounds__(256) void attn_pv_kernel()
{
    __shared__ float As[2][128 * AS_LD];
    __shared__ float Bs[2][16 * VS_LD];

    int z = blockIdx.y;
    int b = z >> 4, h = z & 15;
    int mBase = blockIdx.x * 128;
    int tbase = b * S_LEN;
    int tx = threadIdx.x;
    int warp = tx >> 5, wm = warp >> 1, wn = warp & 1;

    FragC c[2][2];
#pragma unroll
    for (int mi = 0; mi < 2; mi++)
#pragma unroll
        for (int ni = 0; ni < 2; ni++) wmma::fill_fragment(c[mi][ni], 0.f);

    int arow = tx >> 1, acol = (tx & 1) * 8;
    int brow = tx >> 4, bcol = (tx & 15) * 4;
    const float* aP = g_scores + (size_t)z * S_LEN * S_LEN + (size_t)(mBase + arow) * S_LEN + acol;
    const float* bP = g_qkv + (size_t)(tbase + brow) * 3072 + 2048 + h * 64 + bcol;
    const int nt = S_LEN >> 4;

    cp16(&As[0][arow * AS_LD + acol],     aP,     true);
    cp16(&As[0][arow * AS_LD + acol + 4], aP + 4, true);
    cp16(&Bs[0][brow * VS_LD + bcol],     bP,     true);
    cp_commit();

    for (int t = 0; t < nt; t++) {
        int cur = t & 1, nxt = cur ^ 1;
        if (t + 1 < nt) {
            const float* a2 = aP + (t + 1) * 16;
            const float* b2 = bP + (size_t)(t + 1) * 16 * 3072;
            cp16(&As[nxt][arow * AS_LD + acol],     a2,     true);
            cp16(&As[nxt][arow * AS_LD + acol + 4], a2 + 4, true);
            cp16(&Bs[nxt][brow * VS_LD + bcol],     b2,     true);
            cp_commit();
            cp_wait1();
        } else cp_wait0();
        __syncthreads();
#pragma unroll
        for (int ks = 0; ks < 2; ks++) {
            FragA a[2]; FragB bb[2];
            load_a_frags(a, As[cur], wm, ks);
#pragma unroll
            for (int ni = 0; ni < 2; ni++) {
                wmma::load_matrix_sync(bb[ni], &Bs[cur][(ks * 8) * VS_LD + wn * 32 + ni * 16], VS_LD);
#pragma unroll
                for (int i = 0; i < bb[ni].num_elements; i++)
                    bb[ni].x[i] = wmma::__float_to_tf32(bb[ni].x[i]);
            }
#pragma unroll
            for (int mi = 0; mi < 2; mi++)
#pragma unroll
                for (int ni = 0; ni < 2; ni++)
                    wmma::mma_sync(c[mi][ni], a[mi], bb[ni], c[mi][ni]);
        }
        __syncthreads();
    }

#pragma unroll
    for (int mi = 0; mi < 2; mi++)
#pragma unroll
        for (int ni = 0; ni < 2; ni++)
            wmma::store_matrix_sync(
                &g_ctx[(size_t)(tbase + mBase + wm * 32 + mi * 16) * H_DIM + h * 64 + wn * 32 + ni * 16],
                c[mi][ni], H_DIM, wmma::mem_row_major);
}

// ================= MoE gate_up fused silu — 128x64 tile (low reg pressure) ===========
// grid (INTER/64 ntiles, 16 mtiles, 8 experts); warps 4m x 2n, warp tile 32x32 (g & u)
__global__ __launch_bounds__(256) void moe_gateup_kernel(const float* __restrict__ Wgu)
{
    extern __shared__ float sm[];
    float* As = sm;                       // 2 x 128 x 24  (24.6 KB)
    float* Bg = sm + 2 * 128 * AS_LD;     // 2 x 16 x 72   (9.2 KB)
    float* Bu = Bg + 2 * 16 * GS_LD;      // 2 x 16 x 72   (9.2 KB)
    float* Cs = sm;                       // epilogue reuse: 128 x 68 (34.8 KB)
    __shared__ int sPid[128];

    int e = blockIdx.z;
    int count = g_cnt[e];
    int mBase = blockIdx.y * 128;
    if (mBase >= count) return;
    int nBase = blockIdx.x * 64;          // within INTER

    int tx = threadIdx.x;
    if (tx < 128) {
        int r = mBase + tx;
        sPid[tx] = (r < count) ? g_rows[e * T_TOK + r] : -1;
    }
    __syncthreads();

    const float* B = Wgu + (size_t)e * H_DIM * GU2;
    int warp = tx >> 5, wm = warp >> 1, wn = warp & 1;

    FragC cg[2][2], cu[2][2];
#pragma unroll
    for (int mi = 0; mi < 2; mi++)
#pragma unroll
        for (int ni = 0; ni < 2; ni++) { wmma::fill_fragment(cg[mi][ni], 0.f); wmma::fill_fragment(cu[mi][ni], 0.f); }

    int arow = tx >> 1, acol = (tx & 1) * 8;
    int brow = tx >> 4, bcol = (tx & 15) * 4;   // 16 rows x 64 cols, one cp16 each
    int pidA = sPid[arow];
    bool valid = (pidA >= 0);
    const float* aP = g_hs + (valid ? (size_t)(pidA >> 1) * H_DIM : 0) + acol;
    const float* bgP = B + (size_t)brow * GU2 + nBase + bcol;
    const float* buP = bgP + INTER;
    const int nt = H_DIM >> 4;   // 64

    cp16(&As[0 * 128 * AS_LD + arow * AS_LD + acol],     aP,     valid);
    cp16(&As[0 * 128 * AS_LD + arow * AS_LD + acol + 4], aP + 4, valid);
    cp16(&Bg[0 * 16 * GS_LD + brow * GS_LD + bcol],      bgP,    true);
    cp16(&Bu[0 * 16 * GS_LD + brow * GS_LD + bcol],      buP,    true);
    cp_commit();

    for (int t = 0; t < nt; t++) {
        int cur = t & 1, nxt = cur ^ 1;
        if (t + 1 < nt) {
            const float* a2 = aP + (t + 1) * 16;
            const float* bg2 = bgP + (size_t)(t + 1) * 16 * GU2;
            const float* bu2 = buP + (size_t)(t + 1) * 16 * GU2;
            cp16(&As[nxt * 128 * AS_LD + arow * AS_LD + acol],     a2,     valid);
            cp16(&As[nxt * 128 * AS_LD + arow * AS_LD + acol + 4], a2 + 4, valid);
            cp16(&Bg[nxt * 16 * GS_LD + brow * GS_LD + bcol],      bg2,    true);
            cp16(&Bu[nxt * 16 * GS_LD + brow * GS_LD + bcol],      bu2,    true);
            cp_commit();
            cp_wait1();
        } else cp_wait0();
        __syncthreads();
#pragma unroll
        for (int ks = 0; ks < 2; ks++) {
            FragA a[2];
            load_a_frags(a, &As[cur * 128 * AS_LD], wm, ks);
#pragma unroll
            for (int ni = 0; ni < 2; ni++) {
                FragB bg;
                wmma::load_matrix_sync(bg, &Bg[cur * 16 * GS_LD + (ks * 8) * GS_LD + wn * 32 + ni * 16], GS_LD);
#pragma unroll
                for (int i = 0; i < bg.num_elements; i++) bg.x[i] = wmma::__float_to_tf32(bg.x[i]);
#pragma unroll
                for (int mi = 0; mi < 2; mi++)
                    wmma::mma_sync(cg[mi][ni], a[mi], bg, cg[mi][ni]);
                FragB bu;
                wmma::load_matrix_sync(bu, &Bu[cur * 16 * GS_LD + (ks * 8) * GS_LD + wn * 32 + ni * 16], GS_LD);
#pragma unroll
                for (int i = 0; i < bu.num_elements; i++) bu.x[i] = wmma::__float_to_tf32(bu.x[i]);
#pragma unroll
                for (int mi = 0; mi < 2; mi++)
                    wmma::mma_sync(cu[mi][ni], a[mi], bu, cu[mi][ni]);
            }
        }
        __syncthreads();
    }

    // silu in-fragment, stage, scatter
#pragma unroll
    for (int mi = 0; mi < 2; mi++)
#pragma unroll
        for (int ni = 0; ni < 2; ni++) {
#pragma unroll
            for (int i = 0; i < cg[mi][ni].num_elements; i++) {
                float g = cg[mi][ni].x[i];
                cg[mi][ni].x[i] = g / (1.f + __expf(-g)) * cu[mi][ni].x[i];
            }
            wmma::store_matrix_sync(&Cs[(wm * 32 + mi * 16) * GC_LD + wn * 32 + ni * 16],
                                    cg[mi][ni], GC_LD, wmma::mem_row_major);
        }
    __syncthreads();

    int orow = tx >> 1, ocol = (tx & 1) * 32;
    int pid = sPid[orow];
    if (pid >= 0) {
        float* dst = g_act + (size_t)pid * INTER + nBase + ocol;
        const float* src = &Cs[orow * GC_LD + ocol];
#pragma unroll
        for (int i = 0; i < 8; i++)
            *(float4*)(dst + i * 4) = *(const float4*)(src + i * 4);
    }
}

// ================= MoE down =================
__global__ __launch_bounds__(256) void moe_down_kernel(const float* __restrict__ Wd)
{
    extern __shared__ float sm[];
    float* As = sm;
    float* Bs = sm + 2 * 128 * AS_LD;
    float* Cs = sm;
    __shared__ int sPid[128];

    int e = blockIdx.z;
    int count = g_cnt[e];
    int mBase = blockIdx.y * 128;
    if (mBase >= count) return;
    int colBase = blockIdx.x * 128;

    int tx = threadIdx.x;
    if (tx < 128) {
        int r = mBase + tx;
        sPid[tx] = (r < count) ? g_rows[e * T_TOK + r] : -1;
    }
    __syncthreads();

    const float* B = Wd + (size_t)e * INTER * H_DIM;
    int warp = tx >> 5, wm = warp >> 1, wn = warp & 1;

    FragC c[2][4];
#pragma unroll
    for (int mi = 0; mi < 2; mi++)
#pragma unroll
        for (int ni = 0; ni < 4; ni++) wmma::fill_fragment(c[mi][ni], 0.f);

    int arow = tx >> 1, acol = (tx & 1) * 8;
    int brow = tx >> 4, bcol = (tx & 15) * 8;
    int pidA = sPid[arow];
    bool valid = (pidA >= 0);
    const float* aP = g_act + (valid ? (size_t)pidA * INTER : 0) + acol;
    const float* bP = B + (size_t)brow * H_DIM + colBase + bcol;
    const int nt = INTER >> 4;

    cp16(&As[0 * 128 * AS_LD + arow * AS_LD + acol],     aP,     valid);
    cp16(&As[0 * 128 * AS_LD + arow * AS_LD + acol + 4], aP + 4, valid);
    cp16(&Bs[0 * 16 * BS_LD + brow * BS_LD + bcol],      bP,     true);
    cp16(&Bs[0 * 16 * BS_LD + brow * BS_LD + bcol + 4],  bP + 4, true);
    cp_commit();

    for (int t = 0; t < nt; t++) {
        int cur = t & 1, nxt = cur ^ 1;
        if (t + 1 < nt) {
            const float* a2 = aP + (t + 1) * 16;
            const float* b2 = bP + (size_t)(t + 1) * 16 * H_DIM;
            cp16(&As[nxt * 128 * AS_LD + arow * AS_LD + acol],     a2,     valid);
            cp16(&As[nxt * 128 * AS_LD + arow * AS_LD + acol + 4], a2 + 4, valid);
            cp16(&Bs[nxt * 16 * BS_LD + brow * BS_LD + bcol],      b2,     true);
            cp16(&Bs[nxt * 16 * BS_LD + brow * BS_LD + bcol + 4],  b2 + 4, true);
            cp_commit();
            cp_wait1();
        } else cp_wait0();
        __syncthreads();
#pragma unroll
        for (int ks = 0; ks < 2; ks++) {
            FragA a[2]; FragB b[4];
            load_a_frags(a, &As[cur * 128 * AS_LD], wm, ks);
            load_b_frags(b, &Bs[cur * 16 * BS_LD], wn, ks);
#pragma unroll
            for (int mi = 0; mi < 2; mi++)
#pragma unroll
                for (int ni = 0; ni < 4; ni++)
                    wmma::mma_sync(c[mi][ni], a[mi], b[ni], c[mi][ni]);
        }
        __syncthreads();
    }

#pragma unroll
    for (int mi = 0; mi < 2; mi++)
#pragma unroll
        for (int ni = 0; ni < 4; ni++)
            wmma::store_matrix_sync(&Cs[(wm * 32 + mi * 16) * CS_LD + wn * 64 + ni * 16],
                                    c[mi][ni], CS_LD, wmma::mem_row_major);
    __syncthreads();

    int orow = tx >> 1, ocol = (tx & 1) * 64;
    int pid = sPid[orow];
    if (pid >= 0) {
        float scale = g_pairw[pid];
        float* dst = g_ypair + (size_t)pid * H_DIM + colBase + ocol;
        const float* src = &Cs[orow * CS_LD + ocol];
#pragma unroll
        for (int i = 0; i < 16; i++) {
            float4 v = *(const float4*)(src + i * 4);
            v.x *= scale; v.y *= scale; v.z *= scale; v.w *= scale;
            *(float4*)(dst + i * 4) = v;
        }
    }
}

// ---------------- RoPE ----------------
__global__ void rope_kernel(const float* __restrict__ cosp, const float* __restrict__ sinp)
{
    int idx = blockIdx.x * blockDim.x + threadIdx.x;
    if (idx >= T_TOK * NHEAD * 32) return;
    int d = idx & 31;
    int n = (idx >> 5) & 15;
    int t = idx >> 9;
    int s = t & (S_LEN - 1);
    float c1 = cosp[s * 64 + d],      s1 = sinp[s * 64 + d];
    float c2 = cosp[s * 64 + d + 32], s2 = sinp[s * 64 + d + 32];
    size_t base = (size_t)t * 3072 + n * 64 + d;
    float x1 = g_qkv[base], x2 = g_qkv[base + 32];
    g_qkv[base]      = x1 * c1 - x2 * s1;
    g_qkv[base + 32] = x2 * c2 + x1 * s2;
    base += 1024;
    x1 = g_qkv[base]; x2 = g_qkv[base + 32];
    g_qkv[base]      = x1 * c1 - x2 * s1;
    g_qkv[base + 32] = x2 * c2 + x1 * s2;
}

// ---------------- block reduce ----------------
__device__ __forceinline__ float blockReduceSum(float v)
{
    __shared__ float red[8];
    int lane = threadIdx.x & 31, warp = threadIdx.x >> 5;
#pragma unroll
    for (int o = 16; o; o >>= 1) v += __shfl_xor_sync(0xffffffffu, v, o);
    if (lane == 0) red[warp] = v;
    __syncthreads();
    if (warp == 0) {
        float t = (lane < 8) ? red[lane] : 0.f;
#pragma unroll
        for (int o = 4; o; o >>= 1) t += __shfl_xor_sync(0xffffffffu, t, o);
        if (lane == 0) red[0] = t;
    }
    __syncthreads();
    return red[0];
}

// ---------------- add + rmsnorm ----------------
__global__ __launch_bounds__(256) void addnorm_kernel(
    const float* __restrict__ a, const float* __restrict__ b, float* __restrict__ out)
{
    int t = blockIdx.x, tx = threadIdx.x;
    const float* ap = a + (size_t)t * H_DIM;
    const float* bp = b + (size_t)t * H_DIM;
    float v[4]; float ss = 0.f;
#pragma unroll
    for (int j = 0; j < 4; j++) {
        int i = tx + j * 256;
        float x = ap[i] + bp[i];
        v[j] = x; ss += x * x;
    }
    float tot = blockReduceSum(ss);
    float scale = rsqrtf(tot * (1.f / H_DIM) + 1e-5f);
    float* op = out + (size_t)t * H_DIM;
#pragma unroll
    for (int j = 0; j < 4; j++) op[tx + j * 256] = v[j] * scale;
}

// ---------------- routing ----------------
__global__ void zerocnt_kernel() { if (threadIdx.x < NEXP) g_cnt[threadIdx.x] = 0; }

__global__ void route_kernel(const float* __restrict__ wg)
{
    int t = blockIdx.x, lane = threadIdx.x;
    float p[8];
#pragma unroll
    for (int e = 0; e < 8; e++) p[e] = 0.f;
    const float* x = g_hs + (size_t)t * H_DIM;
    for (int h = lane; h < H_DIM; h += 32) {
        float xv = x[h];
#pragma unroll
        for (int e = 0; e < 8; e++) p[e] += xv * wg[h * 8 + e];
    }
#pragma unroll
    for (int e = 0; e < 8; e++)
#pragma unroll
        for (int o = 16; o; o >>= 1) p[e] += __shfl_xor_sync(0xffffffffu, p[e], o);

    if (lane == 0) {
        int e0 = 0; float l0 = p[0];
        for (int e = 1; e < 8; e++) if (p[e] > l0) { l0 = p[e]; e0 = e; }
        int e1 = -1; float l1 = -1e30f;
        for (int e = 0; e < 8; e++) if (e != e0 && p[e] > l1) { l1 = p[e]; e1 = e; }
        float w0 = 1.f / (1.f + expf(l1 - l0));
        float w1 = 1.f - w0;
        int pos0 = atomicAdd(&g_cnt[e0], 1);
        g_rows[e0 * T_TOK + pos0] = t * 2;
        g_pairw[t * 2] = w0;
        int pos1 = atomicAdd(&g_cnt[e1], 1);
        g_rows[e1 * T_TOK + pos1] = t * 2 + 1;
        g_pairw[t * 2 + 1] = w1;
    }
}

// ---------------- final rmsnorm ----------------
__global__ __launch_bounds__(256) void final_kernel(float* __restrict__ out)
{
    int t = blockIdx.x, tx = threadIdx.x;
    const float* hs = g_hs + (size_t)t * H_DIM;
    const float* y0 = g_ypair + (size_t)(t * 2) * H_DIM;
    const float* y1 = y0 + H_DIM;
    float v[4]; float ss = 0.f;
#pragma unroll
    for (int j = 0; j < 4; j++) {
        int i = tx + j * 256;
        float x = hs[i] + y0[i] + y1[i];
        v[j] = x; ss += x * x;
    }
    float tot = blockReduceSum(ss);
    float scale = rsqrtf(tot * (1.f / H_DIM) + 1e-5f);
    float* op = out + (size_t)t * H_DIM;
#pragma unroll
    for (int j = 0; j < 4; j++) op[tx + j * 256] = v[j] * scale;
}

// ---------------- launch ----------------
extern "C" void kernel_launch(void* const* d_in, const int* in_sizes, int n_in,
                              void* d_out, int out_size)
{
    const float* hidden = (const float*)d_in[0];
    const float* cosp   = (const float*)d_in[1];
    const float* sinp   = (const float*)d_in[2];
    const float* w_qkv  = (const float*)d_in[3];
    const float* w_o    = (const float*)d_in[4];
    const float* w_gate = (const float*)d_in[5];
    const float* w_gu   = (const float*)d_in[6];
    const float* w_down = (const float*)d_in[7];
    float* out = (float*)d_out;

    float* qkv_ptr; cudaGetSymbolAddress((void**)&qkv_ptr, g_qkv);
    float* ctx_ptr; cudaGetSymbolAddress((void**)&ctx_ptr, g_ctx);
    float* tmp_ptr; cudaGetSymbolAddress((void**)&tmp_ptr, g_tmp);
    float* hs_ptr;  cudaGetSymbolAddress((void**)&hs_ptr,  g_hs);

    const int GU_SMEM   = (2 * 128 * AS_LD + 4 * 16 * GS_LD) * 4;  // 43 KB mainloop (> epilogue 34.8 KB)
    const int DOWN_SMEM = 128 * CS_LD * 4;                          // 67.6 KB
    static bool attrs_set = false;
    if (!attrs_set) {
        cudaFuncSetAttribute(moe_gateup_kernel, cudaFuncAttributeMaxDynamicSharedMemorySize, GU_SMEM);
        cudaFuncSetAttribute(moe_down_kernel,   cudaFuncAttributeMaxDynamicSharedMemorySize, DOWN_SMEM);
        attrs_set = true;
    }

    // 1. QKV projection
    gemm_tf32_kernel<<<dim3(3072 / 128, 2048 / 128), 256>>>(hidden, w_qkv, qkv_ptr, 2048, 3072, 1024);

    // 2. RoPE
    rope_kernel<<<(T_TOK * NHEAD * 32) / 256, 256>>>(cosp, sinp);

    // 3. attention
    attn_qk_kernel<<<dim3(8, 8, 32), 256>>>();
    softmax_kernel<<<(2 * NHEAD * S_LEN) / 8, 256>>>();
    attn_pv_kernel<<<dim3(8, 32), 256>>>();

    // 4. O projection
    gemm_tf32_kernel<<<dim3(1024 / 128, 2048 / 128), 256>>>(ctx_ptr, w_o, tmp_ptr, 2048, 1024, 1024);

    // 5. hs = rmsnorm(x + attn_out)
    addnorm_kernel<<<T_TOK, 256>>>(hidden, tmp_ptr, hs_ptr);

    // 6. routing
    zerocnt_kernel<<<1, 32>>>();
    route_kernel<<<T_TOK, 32>>>(w_gate);

    // 7. fused gate_up + silu -> g_act  (64-col tiles, no spills)
    moe_gateup_kernel<<<dim3(INTER / 64, 2048 / 128, NEXP), 256, GU_SMEM>>>(w_gu);

    // 8. down proj (weighted) -> g_ypair
    moe_down_kernel<<<dim3(1024 / 128, 2048 / 128, NEXP), 256, DOWN_SMEM>>>(w_down);

    // 9. out = rmsnorm(hs + mixed)
    final_kernel<<<T_TOK, 256>>>(out);
}

// round 8
// speedup vs baseline: 2.1760x; 1.0274x over previous
#include <cuda_runtime.h>
#include <mma.h>
#include <math.h>
#include <cstdint>

using namespace nvcuda;

// ---------------- problem constants ----------------
#define T_TOK 2048
#define S_LEN 1024
#define H_DIM 1024
#define NHEAD 16
#define HD    64
#define NEXP  8
#define INTER 2816
#define GU2   (2*INTER)

// ---------------- device scratch ----------------
__device__ float g_qkv [(size_t)T_TOK * 3 * H_DIM];
__device__ float g_ctx [(size_t)T_TOK * H_DIM];
__device__ float g_tmp [(size_t)T_TOK * H_DIM];
__device__ float g_hs  [(size_t)T_TOK * H_DIM];
__device__ float g_act [(size_t)T_TOK * 2 * INTER];
__device__ float g_ypair[(size_t)T_TOK * 2 * H_DIM];
__device__ float g_scores[(size_t)2 * NHEAD * S_LEN * S_LEN];
__device__ float g_pairw[T_TOK * 2];
__device__ int   g_cnt [NEXP];
__device__ int   g_rows[NEXP * T_TOK];

// ---------------- cp.async helpers ----------------
__device__ __forceinline__ void cp16(float* s, const float* g, bool pred) {
    unsigned int sa = (unsigned int)__cvta_generic_to_shared(s);
    int sz = pred ? 16 : 0;
    asm volatile("cp.async.cg.shared.global [%0], [%1], 16, %2;\n" :: "r"(sa), "l"(g), "r"(sz));
}
__device__ __forceinline__ void cp_commit() { asm volatile("cp.async.commit_group;\n"); }
__device__ __forceinline__ void cp_wait1()  { asm volatile("cp.async.wait_group 1;\n" ::: "memory"); }
__device__ __forceinline__ void cp_wait0()  { asm volatile("cp.async.wait_group 0;\n" ::: "memory"); }

#define AS_LD 24
#define BS_LD 136
#define CS_LD 132
#define KS_LD 24
#define VS_LD 72
#define GS_LD 72
#define GC_LD 68

typedef wmma::fragment<wmma::matrix_a, 16, 16, 8, wmma::precision::tf32, wmma::row_major> FragA;
typedef wmma::fragment<wmma::matrix_b, 16, 16, 8, wmma::precision::tf32, wmma::row_major> FragB;
typedef wmma::fragment<wmma::matrix_b, 16, 16, 8, wmma::precision::tf32, wmma::col_major> FragBc;
typedef wmma::fragment<wmma::accumulator, 16, 16, 8, float> FragC;

__device__ __forceinline__ void load_a_frags(FragA a[2], const float* As, int wm, int ks) {
#pragma unroll
    for (int mi = 0; mi < 2; mi++) {
        wmma::load_matrix_sync(a[mi], &As[(wm * 32 + mi * 16) * AS_LD + ks * 8], AS_LD);
#pragma unroll
        for (int i = 0; i < a[mi].num_elements; i++)
            a[mi].x[i] = wmma::__float_to_tf32(a[mi].x[i]);
    }
}
__device__ __forceinline__ void load_b_frags(FragB b[4], const float* Bs, int wn, int ks) {
#pragma unroll
    for (int ni = 0; ni < 4; ni++) {
        wmma::load_matrix_sync(b[ni], &Bs[(ks * 8) * BS_LD + wn * 64 + ni * 16], BS_LD);
#pragma unroll
        for (int i = 0; i < b[ni].num_elements; i++)
            b[ni].x[i] = wmma::__float_to_tf32(b[ni].x[i]);
    }
}

// ================= plain TF32 GEMM, 2-stage cp.async, 2 CTAs/SM =================
__global__ __launch_bounds__(256, 2) void gemm_tf32_kernel(
    const float* __restrict__ A, const float* __restrict__ B,
    float* __restrict__ C, int M, int N, int K)
{
    __shared__ float As[2][128 * AS_LD];
    __shared__ float Bs[2][16 * BS_LD];

    int tx = threadIdx.x;
    int rowBase = blockIdx.y * 128;
    int colBase = blockIdx.x * 128;
    int warp = tx >> 5, wm = warp >> 1, wn = warp & 1;

    FragC c[2][4];
#pragma unroll
    for (int mi = 0; mi < 2; mi++)
#pragma unroll
        for (int ni = 0; ni < 4; ni++) wmma::fill_fragment(c[mi][ni], 0.f);

    int arow = tx >> 1, acol = (tx & 1) * 8;
    int brow = tx >> 4, bcol = (tx & 15) * 8;
    const float* aP = A + (size_t)(rowBase + arow) * K + acol;
    const float* bP = B + (size_t)brow * N + colBase + bcol;
    int nt = K >> 4;

    cp16(&As[0][arow * AS_LD + acol],     aP,     true);
    cp16(&As[0][arow * AS_LD + acol + 4], aP + 4, true);
    cp16(&Bs[0][brow * BS_LD + bcol],     bP,     true);
    cp16(&Bs[0][brow * BS_LD + bcol + 4], bP + 4, true);
    cp_commit();

    for (int t = 0; t < nt; t++) {
        int cur = t & 1, nxt = cur ^ 1;
        if (t + 1 < nt) {
            const float* a2 = aP + (t + 1) * 16;
            const float* b2 = bP + (size_t)(t + 1) * 16 * N;
            cp16(&As[nxt][arow * AS_LD + acol],     a2,     true);
            cp16(&As[nxt][arow * AS_LD + acol + 4], a2 + 4, true);
            cp16(&Bs[nxt][brow * BS_LD + bcol],     b2,     true);
            cp16(&Bs[nxt][brow * BS_LD + bcol + 4], b2 + 4, true);
            cp_commit();
            cp_wait1();
        } else cp_wait0();
        __syncthreads();
#pragma unroll
        for (int ks = 0; ks < 2; ks++) {
            FragA a[2]; FragB b[4];
            load_a_frags(a, As[cur], wm, ks);
            load_b_frags(b, Bs[cur], wn, ks);
#pragma unroll
            for (int mi = 0; mi < 2; mi++)
#pragma unroll
                for (int ni = 0; ni < 4; ni++)
                    wmma::mma_sync(c[mi][ni], a[mi], b[ni], c[mi][ni]);
        }
        __syncthreads();
    }
#pragma unroll
    for (int mi = 0; mi < 2; mi++)
#pragma unroll
        for (int ni = 0; ni < 4; ni++)
            wmma::store_matrix_sync(
                &C[(size_t)(rowBase + wm * 32 + mi * 16) * N + colBase + wn * 64 + ni * 16],
                c[mi][ni], N, wmma::mem_row_major);
}

// ================= attention scores: S = 0.125 * Q @ K^T =================
__global__ __launch_bounds__(256, 2) void attn_qk_kernel()
{
    __shared__ float As[2][128 * AS_LD];
    __shared__ float Bs[2][128 * KS_LD];

    int z = blockIdx.z;
    int b = z >> 4, h = z & 15;
    int qBase = blockIdx.y * 128, kBase = blockIdx.x * 128;
    int tbase = b * S_LEN;
    int tx = threadIdx.x;
    int warp = tx >> 5, wm = warp >> 1, wn = warp & 1;

    FragC c[2][4];
#pragma unroll
    for (int mi = 0; mi < 2; mi++)
#pragma unroll
        for (int ni = 0; ni < 4; ni++) wmma::fill_fragment(c[mi][ni], 0.f);

    int arow = tx >> 1, acol = (tx & 1) * 8;
    const float* aP = g_qkv + (size_t)(tbase + qBase + arow) * 3072 + h * 64 + acol;
    const float* bP = g_qkv + (size_t)(tbase + kBase + arow) * 3072 + 1024 + h * 64 + acol;
    const int nt = 4;

    cp16(&As[0][arow * AS_LD + acol],     aP,     true);
    cp16(&As[0][arow * AS_LD + acol + 4], aP + 4, true);
    cp16(&Bs[0][arow * KS_LD + acol],     bP,     true);
    cp16(&Bs[0][arow * KS_LD + acol + 4], bP + 4, true);
    cp_commit();

    for (int t = 0; t < nt; t++) {
        int cur = t & 1, nxt = cur ^ 1;
        if (t + 1 < nt) {
            const float* a2 = aP + (t + 1) * 16;
            const float* b2 = bP + (t + 1) * 16;
            cp16(&As[nxt][arow * AS_LD + acol],     a2,     true);
            cp16(&As[nxt][arow * AS_LD + acol + 4], a2 + 4, true);
            cp16(&Bs[nxt][arow * KS_LD + acol],     b2,     true);
            cp16(&Bs[nxt][arow * KS_LD + acol + 4], b2 + 4, true);
            cp_commit();
            cp_wait1();
        } else cp_wait0();
        __syncthreads();
#pragma unroll
        for (int ks = 0; ks < 2; ks++) {
            FragA a[2]; FragBc bb[4];
            load_a_frags(a, As[cur], wm, ks);
#pragma unroll
            for (int ni = 0; ni < 4; ni++) {
                wmma::load_matrix_sync(bb[ni], &Bs[cur][(wn * 64 + ni * 16) * KS_LD + ks * 8], KS_LD);
#pragma unroll
                for (int i = 0; i < bb[ni].num_elements; i++)
                    bb[ni].x[i] = wmma::__float_to_tf32(bb[ni].x[i]);
            }
#pragma unroll
            for (int mi = 0; mi < 2; mi++)
#pragma unroll
                for (int ni = 0; ni < 4; ni++)
                    wmma::mma_sync(c[mi][ni], a[mi], bb[ni], c[mi][ni]);
        }
        __syncthreads();
    }

    float* Sbase = g_scores + (size_t)z * S_LEN * S_LEN;
#pragma unroll
    for (int mi = 0; mi < 2; mi++)
#pragma unroll
        for (int ni = 0; ni < 4; ni++) {
#pragma unroll
            for (int i = 0; i < c[mi][ni].num_elements; i++) c[mi][ni].x[i] *= 0.125f;
            wmma::store_matrix_sync(
                &Sbase[(size_t)(qBase + wm * 32 + mi * 16) * S_LEN + kBase + wn * 64 + ni * 16],
                c[mi][ni], S_LEN, wmma::mem_row_major);
        }
}

// ================= row softmax =================
__global__ __launch_bounds__(256) void softmax_kernel()
{
    int row = blockIdx.x * 8 + (threadIdx.x >> 5);
    int lane = threadIdx.x & 31;
    float* p = g_scores + (size_t)row * S_LEN;

    float4 v[8];
    float mx = -1e30f;
#pragma unroll
    for (int i = 0; i < 8; i++) {
        v[i] = *(const float4*)(p + (i * 32 + lane) * 4);
        mx = fmaxf(mx, fmaxf(fmaxf(v[i].x, v[i].y), fmaxf(v[i].z, v[i].w)));
    }
#pragma unroll
    for (int o = 16; o; o >>= 1) mx = fmaxf(mx, __shfl_xor_sync(0xffffffffu, mx, o));
    float sum = 0.f;
#pragma unroll
    for (int i = 0; i < 8; i++) {
        v[i].x = __expf(v[i].x - mx); v[i].y = __expf(v[i].y - mx);
        v[i].z = __expf(v[i].z - mx); v[i].w = __expf(v[i].w - mx);
        sum += v[i].x + v[i].y + v[i].z + v[i].w;
    }
#pragma unroll
    for (int o = 16; o; o >>= 1) sum += __shfl_xor_sync(0xffffffffu, sum, o);
    float inv = 1.f / sum;
#pragma unroll
    for (int i = 0; i < 8; i++) {
        v[i].x *= inv; v[i].y *= inv; v[i].z *= inv; v[i].w *= inv;
        *(float4*)(p + (i * 32 + lane) * 4) = v[i];
    }
}

// ================= attention PV =================
__global__ __launch_bounds__(256, 2) void attn_pv_kernel()
{
    __shared__ float As[2][128 * AS_LD];
    __shared__ float Bs[2][16 * VS_LD];

    int z = blockIdx.y;
    int b = z >> 4, h = z & 15;
    int mBase = blockIdx.x * 128;
    int tbase = b * S_LEN;
    int tx = threadIdx.x;
    int warp = tx >> 5, wm = warp >> 1, wn = warp & 1;

    FragC c[2][2];
#pragma unroll
    for (int mi = 0; mi < 2; mi++)
#pragma unroll
        for (int ni = 0; ni < 2; ni++) wmma::fill_fragment(c[mi][ni], 0.f);

    int arow = tx >> 1, acol = (tx & 1) * 8;
    int brow = tx >> 4, bcol = (tx & 15) * 4;
    const float* aP = g_scores + (size_t)z * S_LEN * S_LEN + (size_t)(mBase + arow) * S_LEN + acol;
    const float* bP = g_qkv + (size_t)(tbase + brow) * 3072 + 2048 + h * 64 + bcol;
    const int nt = S_LEN >> 4;

    cp16(&As[0][arow * AS_LD + acol],     aP,     true);
    cp16(&As[0][arow * AS_LD + acol + 4], aP + 4, true);
    cp16(&Bs[0][brow * VS_LD + bcol],     bP,     true);
    cp_commit();

    for (int t = 0; t < nt; t++) {
        int cur = t & 1, nxt = cur ^ 1;
        if (t + 1 < nt) {
            const float* a2 = aP + (t + 1) * 16;
            const float* b2 = bP + (size_t)(t + 1) * 16 * 3072;
            cp16(&As[nxt][arow * AS_LD + acol],     a2,     true);
            cp16(&As[nxt][arow * AS_LD + acol + 4], a2 + 4, true);
            cp16(&Bs[nxt][brow * VS_LD + bcol],     b2,     true);
            cp_commit();
            cp_wait1();
        } else cp_wait0();
        __syncthreads();
#pragma unroll
        for (int ks = 0; ks < 2; ks++) {
            FragA a[2]; FragB bb[2];
            load_a_frags(a, As[cur], wm, ks);
#pragma unroll
            for (int ni = 0; ni < 2; ni++) {
                wmma::load_matrix_sync(bb[ni], &Bs[cur][(ks * 8) * VS_LD + wn * 32 + ni * 16], VS_LD);
#pragma unroll
                for (int i = 0; i < bb[ni].num_elements; i++)
                    bb[ni].x[i] = wmma::__float_to_tf32(bb[ni].x[i]);
            }
#pragma unroll
            for (int mi = 0; mi < 2; mi++)
#pragma unroll
                for (int ni = 0; ni < 2; ni++)
                    wmma::mma_sync(c[mi][ni], a[mi], bb[ni], c[mi][ni]);
        }
        __syncthreads();
    }

#pragma unroll
    for (int mi = 0; mi < 2; mi++)
#pragma unroll
        for (int ni = 0; ni < 2; ni++)
            wmma::store_matrix_sync(
                &g_ctx[(size_t)(tbase + mBase + wm * 32 + mi * 16) * H_DIM + h * 64 + wn * 32 + ni * 16],
                c[mi][ni], H_DIM, wmma::mem_row_major);
}

// ================= MoE gate_up fused silu — 128x64 tile =================
__global__ __launch_bounds__(256, 2) void moe_gateup_kernel(const float* __restrict__ Wgu)
{
    extern __shared__ float sm[];
    float* As = sm;
    float* Bg = sm + 2 * 128 * AS_LD;
    float* Bu = Bg + 2 * 16 * GS_LD;
    float* Cs = sm;
    __shared__ int sPid[128];

    int e = blockIdx.z;
    int count = g_cnt[e];
    int mBase = blockIdx.y * 128;
    if (mBase >= count) return;
    int nBase = blockIdx.x * 64;

    int tx = threadIdx.x;
    if (tx < 128) {
        int r = mBase + tx;
        sPid[tx] = (r < count) ? g_rows[e * T_TOK + r] : -1;
    }
    __syncthreads();

    const float* B = Wgu + (size_t)e * H_DIM * GU2;
    int warp = tx >> 5, wm = warp >> 1, wn = warp & 1;

    FragC cg[2][2], cu[2][2];
#pragma unroll
    for (int mi = 0; mi < 2; mi++)
#pragma unroll
        for (int ni = 0; ni < 2; ni++) { wmma::fill_fragment(cg[mi][ni], 0.f); wmma::fill_fragment(cu[mi][ni], 0.f); }

    int arow = tx >> 1, acol = (tx & 1) * 8;
    int brow = tx >> 4, bcol = (tx & 15) * 4;
    int pidA = sPid[arow];
    bool valid = (pidA >= 0);
    const float* aP = g_hs + (valid ? (size_t)(pidA >> 1) * H_DIM : 0) + acol;
    const float* bgP = B + (size_t)brow * GU2 + nBase + bcol;
    const float* buP = bgP + INTER;
    const int nt = H_DIM >> 4;

    cp16(&As[0 * 128 * AS_LD + arow * AS_LD + acol],     aP,     valid);
    cp16(&As[0 * 128 * AS_LD + arow * AS_LD + acol + 4], aP + 4, valid);
    cp16(&Bg[0 * 16 * GS_LD + brow * GS_LD + bcol],      bgP,    true);
    cp16(&Bu[0 * 16 * GS_LD + brow * GS_LD + bcol],      buP,    true);
    cp_commit();

    for (int t = 0; t < nt; t++) {
        int cur = t & 1, nxt = cur ^ 1;
        if (t + 1 < nt) {
            const float* a2 = aP + (t + 1) * 16;
            const float* bg2 = bgP + (size_t)(t + 1) * 16 * GU2;
            const float* bu2 = buP + (size_t)(t + 1) * 16 * GU2;
            cp16(&As[nxt * 128 * AS_LD + arow * AS_LD + acol],     a2,     valid);
            cp16(&As[nxt * 128 * AS_LD + arow * AS_LD + acol + 4], a2 + 4, valid);
            cp16(&Bg[nxt * 16 * GS_LD + brow * GS_LD + bcol],      bg2,    true);
            cp16(&Bu[nxt * 16 * GS_LD + brow * GS_LD + bcol],      bu2,    true);
            cp_commit();
            cp_wait1();
        } else cp_wait0();
        __syncthreads();
#pragma unroll
        for (int ks = 0; ks < 2; ks++) {
            FragA a[2];
            load_a_frags(a, &As[cur * 128 * AS_LD], wm, ks);
#pragma unroll
            for (int ni = 0; ni < 2; ni++) {
                FragB bg;
                wmma::load_matrix_sync(bg, &Bg[cur * 16 * GS_LD + (ks * 8) * GS_LD + wn * 32 + ni * 16], GS_LD);
#pragma unroll
                for (int i = 0; i < bg.num_elements; i++) bg.x[i] = wmma::__float_to_tf32(bg.x[i]);
#pragma unroll
                for (int mi = 0; mi < 2; mi++)
                    wmma::mma_sync(cg[mi][ni], a[mi], bg, cg[mi][ni]);
                FragB bu;
                wmma::load_matrix_sync(bu, &Bu[cur * 16 * GS_LD + (ks * 8) * GS_LD + wn * 32 + ni * 16], GS_LD);
#pragma unroll
                for (int i = 0; i < bu.num_elements; i++) bu.x[i] = wmma::__float_to_tf32(bu.x[i]);
#pragma unroll
                for (int mi = 0; mi < 2; mi++)
                    wmma::mma_sync(cu[mi][ni], a[mi], bu, cu[mi][ni]);
            }
        }
        __syncthreads();
    }

#pragma unroll
    for (int mi = 0; mi < 2; mi++)
#pragma unroll
        for (int ni = 0; ni < 2; ni++) {
#pragma unroll
            for (int i = 0; i < cg[mi][ni].num_elements; i++) {
                float g = cg[mi][ni].x[i];
                cg[mi][ni].x[i] = g / (1.f + __expf(-g)) * cu[mi][ni].x[i];
            }
            wmma::store_matrix_sync(&Cs[(wm * 32 + mi * 16) * GC_LD + wn * 32 + ni * 16],
                                    cg[mi][ni], GC_LD, wmma::mem_row_major);
        }
    __syncthreads();

    int orow = tx >> 1, ocol = (tx & 1) * 32;
    int pid = sPid[orow];
    if (pid >= 0) {
        float* dst = g_act + (size_t)pid * INTER + nBase + ocol;
        const float* src = &Cs[orow * GC_LD + ocol];
#pragma unroll
        for (int i = 0; i < 8; i++)
            *(float4*)(dst + i * 4) = *(const float4*)(src + i * 4);
    }
}

// ================= MoE down =================
__global__ __launch_bounds__(256, 2) void moe_down_kernel(const float* __restrict__ Wd)
{
    extern __shared__ float sm[];
    float* As = sm;
    float* Bs = sm + 2 * 128 * AS_LD;
    float* Cs = sm;
    __shared__ int sPid[128];

    int e = blockIdx.z;
    int count = g_cnt[e];
    int mBase = blockIdx.y * 128;
    if (mBase >= count) return;
    int colBase = blockIdx.x * 128;

    int tx = threadIdx.x;
    if (tx < 128) {
        int r = mBase + tx;
        sPid[tx] = (r < count) ? g_rows[e * T_TOK + r] : -1;
    }
    __syncthreads();

    const float* B = Wd + (size_t)e * INTER * H_DIM;
    int warp = tx >> 5, wm = warp >> 1, wn = warp & 1;

    FragC c[2][4];
#pragma unroll
    for (int mi = 0; mi < 2; mi++)
#pragma unroll
        for (int ni = 0; ni < 4; ni++) wmma::fill_fragment(c[mi][ni], 0.f);

    int arow = tx >> 1, acol = (tx & 1) * 8;
    int brow = tx >> 4, bcol = (tx & 15) * 8;
    int pidA = sPid[arow];
    bool valid = (pidA >= 0);
    const float* aP = g_act + (valid ? (size_t)pidA * INTER : 0) + acol;
    const float* bP = B + (size_t)brow * H_DIM + colBase + bcol;
    const int nt = INTER >> 4;

    cp16(&As[0 * 128 * AS_LD + arow * AS_LD + acol],     aP,     valid);
    cp16(&As[0 * 128 * AS_LD + arow * AS_LD + acol + 4], aP + 4, valid);
    cp16(&Bs[0 * 16 * BS_LD + brow * BS_LD + bcol],      bP,     true);
    cp16(&Bs[0 * 16 * BS_LD + brow * BS_LD + bcol + 4],  bP + 4, true);
    cp_commit();

    for (int t = 0; t < nt; t++) {
        int cur = t & 1, nxt = cur ^ 1;
        if (t + 1 < nt) {
            const float* a2 = aP + (t + 1) * 16;
            const float* b2 = bP + (size_t)(t + 1) * 16 * H_DIM;
            cp16(&As[nxt * 128 * AS_LD + arow * AS_LD + acol],     a2,     valid);
            cp16(&As[nxt * 128 * AS_LD + arow * AS_LD + acol + 4], a2 + 4, valid);
            cp16(&Bs[nxt * 16 * BS_LD + brow * BS_LD + bcol],      b2,     true);
            cp16(&Bs[nxt * 16 * BS_LD + brow * BS_LD + bcol + 4],  b2 + 4, true);
            cp_commit();
            cp_wait1();
        } else cp_wait0();
        __syncthreads();
#pragma unroll
        for (int ks = 0; ks < 2; ks++) {
            FragA a[2]; FragB b[4];
            load_a_frags(a, &As[cur * 128 * AS_LD], wm, ks);
            load_b_frags(b, &Bs[cur * 16 * BS_LD], wn, ks);
#pragma unroll
            for (int mi = 0; mi < 2; mi++)
#pragma unroll
                for (int ni = 0; ni < 4; ni++)
                    wmma::mma_sync(c[mi][ni], a[mi], b[ni], c[mi][ni]);
        }
        __syncthreads();
    }

#pragma unroll
    for (int mi = 0; mi < 2; mi++)
#pragma unroll
        for (int ni = 0; ni < 4; ni++)
            wmma::store_matrix_sync(&Cs[(wm * 32 + mi * 16) * CS_LD + wn * 64 + ni * 16],
                                    c[mi][ni], CS_LD, wmma::mem_row_major);
    __syncthreads();

    int orow = tx >> 1, ocol = (tx & 1) * 64;
    int pid = sPid[orow];
    if (pid >= 0) {
        float scale = g_pairw[pid];
        float* dst = g_ypair + (size_t)pid * H_DIM + colBase + ocol;
        const float* src = &Cs[orow * CS_LD + ocol];
#pragma unroll
        for (int i = 0; i < 16; i++) {
            float4 v = *(const float4*)(src + i * 4);
            v.x *= scale; v.y *= scale; v.z *= scale; v.w *= scale;
            *(float4*)(dst + i * 4) = v;
        }
    }
}

// ---------------- RoPE ----------------
__global__ void rope_kernel(const float* __restrict__ cosp, const float* __restrict__ sinp)
{
    int idx = blockIdx.x * blockDim.x + threadIdx.x;
    if (idx >= T_TOK * NHEAD * 32) return;
    int d = idx & 31;
    int n = (idx >> 5) & 15;
    int t = idx >> 9;
    int s = t & (S_LEN - 1);
    float c1 = cosp[s * 64 + d],      s1 = sinp[s * 64 + d];
    float c2 = cosp[s * 64 + d + 32], s2 = sinp[s * 64 + d + 32];
    size_t base = (size_t)t * 3072 + n * 64 + d;
    float x1 = g_qkv[base], x2 = g_qkv[base + 32];
    g_qkv[base]      = x1 * c1 - x2 * s1;
    g_qkv[base + 32] = x2 * c2 + x1 * s2;
    base += 1024;
    x1 = g_qkv[base]; x2 = g_qkv[base + 32];
    g_qkv[base]      = x1 * c1 - x2 * s1;
    g_qkv[base + 32] = x2 * c2 + x1 * s2;
}

// ---------------- block reduce ----------------
__device__ __forceinline__ float blockReduceSum(float v)
{
    __shared__ float red[8];
    int lane = threadIdx.x & 31, warp = threadIdx.x >> 5;
#pragma unroll
    for (int o = 16; o; o >>= 1) v += __shfl_xor_sync(0xffffffffu, v, o);
    if (lane == 0) red[warp] = v;
    __syncthreads();
    if (warp == 0) {
        float t = (lane < 8) ? red[lane] : 0.f;
#pragma unroll
        for (int o = 4; o; o >>= 1) t += __shfl_xor_sync(0xffffffffu, t, o);
        if (lane == 0) red[0] = t;
    }
    __syncthreads();
    return red[0];
}

// ---------------- add + rmsnorm ----------------
__global__ __launch_bounds__(256) void addnorm_kernel(
    const float* __restrict__ a, const float* __restrict__ b, float* __restrict__ out)
{
    int t = blockIdx.x, tx = threadIdx.x;
    const float* ap = a + (size_t)t * H_DIM;
    const float* bp = b + (size_t)t * H_DIM;
    float v[4]; float ss = 0.f;
#pragma unroll
    for (int j = 0; j < 4; j++) {
        int i = tx + j * 256;
        float x = ap[i] + bp[i];
        v[j] = x; ss += x * x;
    }
    float tot = blockReduceSum(ss);
    float scale = rsqrtf(tot * (1.f / H_DIM) + 1e-5f);
    float* op = out + (size_t)t * H_DIM;
#pragma unroll
    for (int j = 0; j < 4; j++) op[tx + j * 256] = v[j] * scale;
}

// ---------------- routing ----------------
__global__ void zerocnt_kernel() { if (threadIdx.x < NEXP) g_cnt[threadIdx.x] = 0; }

__global__ void route_kernel(const float* __restrict__ wg)
{
    int t = blockIdx.x, lane = threadIdx.x;
    float p[8];
#pragma unroll
    for (int e = 0; e < 8; e++) p[e] = 0.f;
    const float* x = g_hs + (size_t)t * H_DIM;
    for (int h = lane; h < H_DIM; h += 32) {
        float xv = x[h];
#pragma unroll
        for (int e = 0; e < 8; e++) p[e] += xv * wg[h * 8 + e];
    }
#pragma unroll
    for (int e = 0; e < 8; e++)
#pragma unroll
        for (int o = 16; o; o >>= 1) p[e] += __shfl_xor_sync(0xffffffffu, p[e], o);

    if (lane == 0) {
        int e0 = 0; float l0 = p[0];
        for (int e = 1; e < 8; e++) if (p[e] > l0) { l0 = p[e]; e0 = e; }
        int e1 = -1; float l1 = -1e30f;
        for (int e = 0; e < 8; e++) if (e != e0 && p[e] > l1) { l1 = p[e]; e1 = e; }
        float w0 = 1.f / (1.f + expf(l1 - l0));
        float w1 = 1.f - w0;
        int pos0 = atomicAdd(&g_cnt[e0], 1);
        g_rows[e0 * T_TOK + pos0] = t * 2;
        g_pairw[t * 2] = w0;
        int pos1 = atomicAdd(&g_cnt[e1], 1);
        g_rows[e1 * T_TOK + pos1] = t * 2 + 1;
        g_pairw[t * 2 + 1] = w1;
    }
}

// ---------------- final rmsnorm ----------------
__global__ __launch_bounds__(256) void final_kernel(float* __restrict__ out)
{
    int t = blockIdx.x, tx = threadIdx.x;
    const float* hs = g_hs + (size_t)t * H_DIM;
    const float* y0 = g_ypair + (size_t)(t * 2) * H_DIM;
    const float* y1 = y0 + H_DIM;
    float v[4]; float ss = 0.f;
#pragma unroll
    for (int j = 0; j < 4; j++) {
        int i = tx + j * 256;
        float x = hs[i] + y0[i] + y1[i];
        v[j] = x; ss += x * x;
    }
    float tot = blockReduceSum(ss);
    float scale = rsqrtf(tot * (1.f / H_DIM) + 1e-5f);
    float* op = out + (size_t)t * H_DIM;
#pragma unroll
    for (int j = 0; j < 4; j++) op[tx + j * 256] = v[j] * scale;
}

// ---------------- launch ----------------
extern "C" void kernel_launch(void* const* d_in, const int* in_sizes, int n_in,
                              void* d_out, int out_size)
{
    const float* hidden = (const float*)d_in[0];
    const float* cosp   = (const float*)d_in[1];
    const float* sinp   = (const float*)d_in[2];
    const float* w_qkv  = (const float*)d_in[3];
    const float* w_o    = (const float*)d_in[4];
    const float* w_gate = (const float*)d_in[5];
    const float* w_gu   = (const float*)d_in[6];
    const float* w_down = (const float*)d_in[7];
    float* out = (float*)d_out;

    float* qkv_ptr; cudaGetSymbolAddress((void**)&qkv_ptr, g_qkv);
    float* ctx_ptr; cudaGetSymbolAddress((void**)&ctx_ptr, g_ctx);
    float* tmp_ptr; cudaGetSymbolAddress((void**)&tmp_ptr, g_tmp);
    float* hs_ptr;  cudaGetSymbolAddress((void**)&hs_ptr,  g_hs);

    const int GU_SMEM   = (2 * 128 * AS_LD + 4 * 16 * GS_LD) * 4;
    const int DOWN_SMEM = 128 * CS_LD * 4;
    static bool attrs_set = false;
    if (!attrs_set) {
        cudaFuncSetAttribute(moe_gateup_kernel, cudaFuncAttributeMaxDynamicSharedMemorySize, GU_SMEM);
        cudaFuncSetAttribute(moe_down_kernel,   cudaFuncAttributeMaxDynamicSharedMemorySize, DOWN_SMEM);
        attrs_set = true;
    }

    // 1. QKV projection
    gemm_tf32_kernel<<<dim3(3072 / 128, 2048 / 128), 256>>>(hidden, w_qkv, qkv_ptr, 2048, 3072, 1024);

    // 2. RoPE
    rope_kernel<<<(T_TOK * NHEAD * 32) / 256, 256>>>(cosp, sinp);

    // 3. attention
    attn_qk_kernel<<<dim3(8, 8, 32), 256>>>();
    softmax_kernel<<<(2 * NHEAD * S_LEN) / 8, 256>>>();
    attn_pv_kernel<<<dim3(8, 32), 256>>>();

    // 4. O projection
    gemm_tf32_kernel<<<dim3(1024 / 128, 2048 / 128), 256>>>(ctx_ptr, w_o, tmp_ptr, 2048, 1024, 1024);

    // 5. hs = rmsnorm(x + attn_out)
    addnorm_kernel<<<T_TOK, 256>>>(hidden, tmp_ptr, hs_ptr);

    // 6. routing
    zerocnt_kernel<<<1, 32>>>();
    route_kernel<<<T_TOK, 32>>>(w_gate);

    // 7. fused gate_up + silu -> g_act
    moe_gateup_kernel<<<dim3(INTER / 64, 2048 / 128, NEXP), 256, GU_SMEM>>>(w_gu);

    // 8. down proj (weighted) -> g_ypair
    moe_down_kernel<<<dim3(1024 / 128, 2048 / 128, NEXP), 256, DOWN_SMEM>>>(w_down);

    // 9. out = rmsnorm(hs + mixed)
    final_kernel<<<T_TOK, 256>>>(out);
}